// round 10
// baseline (speedup 1.0000x reference)
#include <cuda_runtime.h>
#include <cuda_bf16.h>
#include <cstdint>

#define N_NODES 40000
#define N_EDGES 640000
#define D 128
#define NB 157  // ceil(40000/256) scan blocks

// ---------------- scratch (device globals, referenced by symbol only) ----------------
__device__ float g_h[N_NODES * D];            // GEMM output (per layer), fp32
__device__ unsigned short g_xhi[N_NODES * D]; // bf16 split of x
__device__ unsigned short g_xlo[N_NODES * D];
__device__ unsigned short g_yhi[N_NODES * D]; // bf16 split of layer-1 output
__device__ unsigned short g_ylo[N_NODES * D];
__device__ unsigned short g_w1hi[D * D], g_w1lo[D * D];
__device__ unsigned short g_w2hi[D * D], g_w2lo[D * D];
__device__ int   g_deg[N_NODES];
__device__ int   g_rowptr[N_NODES + 1];
__device__ int   g_cursor[N_NODES];
__device__ int   g_srcs[N_EDGES];
__device__ float g_scale[N_EDGES];
__device__ int   g_is32;
__device__ int   g_bsum[NB];
__device__ int   g_boff[NB];

// ---------------- init: zero degree histogram + detect edge_index dtype ----------------
__global__ __launch_bounds__(256) void init_kernel(const int* __restrict__ ei32) {
    int i = blockIdx.x * 256 + threadIdx.x;
    if (i < N_NODES) g_deg[i] = 0;
    if (blockIdx.x == 0) {
        int nz = 0;
        for (int s = threadIdx.x; s < 4096; s += 256)
            nz |= (ei32[2 * s + 1] != 0);
        nz = __syncthreads_or(nz);
        if (threadIdx.x == 0) g_is32 = nz;
    }
}

__device__ __forceinline__ int load_idx(const void* ei, int pos) {
    if (g_is32) return ((const int*)ei)[pos];
    return (int)((const long long*)ei)[pos];
}

__global__ void count_kernel(const void* __restrict__ ei) {
    int e = blockIdx.x * blockDim.x + threadIdx.x;
    if (e >= N_EDGES) return;
    int dst = load_idx(ei, N_EDGES + e);
    if ((unsigned)dst < (unsigned)N_NODES) atomicAdd(&g_deg[dst], 1);
}

__global__ __launch_bounds__(256) void bsum_kernel() {
    int i = blockIdx.x * 256 + threadIdx.x;
    int v = (i < N_NODES) ? g_deg[i] : 0;
#pragma unroll
    for (int off = 16; off > 0; off >>= 1)
        v += __shfl_down_sync(0xffffffffu, v, off);
    __shared__ int ws[8];
    int wid = threadIdx.x >> 5, lane = threadIdx.x & 31;
    if (lane == 0) ws[wid] = v;
    __syncthreads();
    if (threadIdx.x == 0) {
        int s = 0;
#pragma unroll
        for (int w = 0; w < 8; w++) s += ws[w];
        g_bsum[blockIdx.x] = s;
    }
}

__global__ __launch_bounds__(256) void bscan_kernel() {
    int t = threadIdx.x;
    int lane = t & 31, wid = t >> 5;
    int v = (t < NB) ? g_bsum[t] : 0;
    int orig = v;
#pragma unroll
    for (int off = 1; off < 32; off <<= 1) {
        int u = __shfl_up_sync(0xffffffffu, v, off);
        if (lane >= off) v += u;
    }
    __shared__ int wsum[8];
    if (lane == 31) wsum[wid] = v;
    __syncthreads();
    if (wid == 0) {
        int s = (lane < 8) ? wsum[lane] : 0;
#pragma unroll
        for (int off = 1; off < 8; off <<= 1) {
            int u = __shfl_up_sync(0xffffffffu, s, off);
            if (lane >= off) s += u;
        }
        if (lane < 8) wsum[lane] = s;
    }
    __syncthreads();
    int incl = v + (wid > 0 ? wsum[wid - 1] : 0);
    if (t < NB) g_boff[t] = incl - orig;
}

__global__ __launch_bounds__(256) void rowptr_kernel() {
    int i = blockIdx.x * 256 + threadIdx.x;
    int lane = threadIdx.x & 31, wid = threadIdx.x >> 5;
    int v = (i < N_NODES) ? g_deg[i] : 0;
    int orig = v;
#pragma unroll
    for (int off = 1; off < 32; off <<= 1) {
        int u = __shfl_up_sync(0xffffffffu, v, off);
        if (lane >= off) v += u;
    }
    __shared__ int wsum[8];
    if (lane == 31) wsum[wid] = v;
    __syncthreads();
    if (wid == 0) {
        int s = (lane < 8) ? wsum[lane] : 0;
#pragma unroll
        for (int off = 1; off < 8; off <<= 1) {
            int u = __shfl_up_sync(0xffffffffu, s, off);
            if (lane >= off) s += u;
        }
        if (lane < 8) wsum[lane] = s;
    }
    __syncthreads();
    int incl = v + (wid > 0 ? wsum[wid - 1] : 0);
    int excl = incl - orig + g_boff[blockIdx.x];
    if (i < N_NODES) {
        g_rowptr[i] = excl;
        g_cursor[i] = excl;
        if (i == N_NODES - 1) g_rowptr[N_NODES] = excl + orig;
    }
}

__global__ void fill_kernel(const void* __restrict__ ei,
                            const float* __restrict__ ea) {
    int e = blockIdx.x * blockDim.x + threadIdx.x;
    if (e >= N_EDGES) return;
    int src = load_idx(ei, e);
    int dst = load_idx(ei, N_EDGES + e);
    if ((unsigned)dst >= (unsigned)N_NODES) return;
    if ((unsigned)src >= (unsigned)N_NODES) return;
    int pos = atomicAdd(&g_cursor[dst], 1);
    g_srcs[pos]  = src;
    g_scale[pos] = 1.0f / ea[e];
}

// ---------------- f32 -> bf16 hi/lo split converters ----------------
__device__ __forceinline__ void split_bf16(float f, unsigned short& hi, unsigned short& lo) {
    __nv_bfloat16 h = __float2bfloat16(f);
    float r = f - __bfloat162float(h);
    hi = __bfloat16_as_ushort(h);
    lo = __bfloat16_as_ushort(__float2bfloat16(r));
}

__global__ __launch_bounds__(256) void conv_x_kernel(const float* __restrict__ x) {
    int i = blockIdx.x * 256 + threadIdx.x;      // float4 index
    if (i * 4 >= N_NODES * D) return;
    float4 v = reinterpret_cast<const float4*>(x)[i];
    ushort4 hi, lo;
    split_bf16(v.x, hi.x, lo.x); split_bf16(v.y, hi.y, lo.y);
    split_bf16(v.z, hi.z, lo.z); split_bf16(v.w, hi.w, lo.w);
    reinterpret_cast<ushort4*>(g_xhi)[i] = hi;
    reinterpret_cast<ushort4*>(g_xlo)[i] = lo;
}

__global__ __launch_bounds__(256) void conv_w_kernel(const float* __restrict__ W1,
                                                     const float* __restrict__ W2) {
    int i = blockIdx.x * 256 + threadIdx.x;      // 0..8191 (two 4096 float4 sets)
    if (i >= 8192) return;
    const float* src = (i < 4096) ? W1 : W2;
    unsigned short* dh = (i < 4096) ? g_w1hi : g_w2hi;
    unsigned short* dl = (i < 4096) ? g_w1lo : g_w2lo;
    int j = i & 4095;
    float4 v = reinterpret_cast<const float4*>(src)[j];
    ushort4 hi, lo;
    split_bf16(v.x, hi.x, lo.x); split_bf16(v.y, hi.y, lo.y);
    split_bf16(v.z, hi.z, lo.z); split_bf16(v.w, hi.w, lo.w);
    reinterpret_cast<ushort4*>(dh)[j] = hi;
    reinterpret_cast<ushort4*>(dl)[j] = lo;
}

// ---------------- tensor-core GEMM via mma.sync (HMMA bf16, 3-term split) ----------------
// CTA: 128x128 tile, 8 warps (4 m-groups x 2 n-groups), warp tile 32x64.
// K=128 in two 64-chunks. smem: 4 tiles [128][72] bf16 (padded, conflict-free ldmatrix).
#define SP 72                        // padded row stride (bf16 elems)
#define TILE_B (128 * SP * 2)        // bytes per tile = 18432
#define OFF_AHI 0
#define OFF_ALO (TILE_B)
#define OFF_BHI (2 * TILE_B)
#define OFF_BLO (3 * TILE_B)
#define GEMM_SMEM (4 * TILE_B)       // 73728

__device__ __forceinline__ void ldsm4(uint32_t* r, uint32_t addr) {
    asm volatile("ldmatrix.sync.aligned.m8n8.x4.shared.b16 {%0,%1,%2,%3}, [%4];"
                 : "=r"(r[0]), "=r"(r[1]), "=r"(r[2]), "=r"(r[3]) : "r"(addr));
}
__device__ __forceinline__ void mma16816(float* d, const uint32_t* a, uint32_t b0, uint32_t b1) {
    asm volatile(
        "mma.sync.aligned.m16n8k16.row.col.f32.bf16.bf16.f32 "
        "{%0,%1,%2,%3}, {%4,%5,%6,%7}, {%8,%9}, {%0,%1,%2,%3};"
        : "+f"(d[0]), "+f"(d[1]), "+f"(d[2]), "+f"(d[3])
        : "r"(a[0]), "r"(a[1]), "r"(a[2]), "r"(a[3]), "r"(b0), "r"(b1));
}

__global__ __launch_bounds__(256, 2) void gemm_mma_kernel(int layer) {
    extern __shared__ char smem[];
    uint32_t sb;
    asm("{ .reg .u64 t; cvta.to.shared.u64 t, %1; cvt.u32.u64 %0, t; }" : "=r"(sb) : "l"(smem));
    const int tid  = threadIdx.x;
    const int wid  = tid >> 5;
    const int lane = tid & 31;
    const int lane8 = lane & 7;
    const int g     = lane >> 3;
    const int m0 = (wid & 3) * 32;
    const int n0 = (wid >> 2) * 64;
    const int block_row = blockIdx.x * 128;

    const unsigned short* Ah = (layer == 0) ? g_xhi : g_yhi;
    const unsigned short* Al = (layer == 0) ? g_xlo : g_ylo;
    const unsigned short* Bh = (layer == 0) ? g_w1hi : g_w2hi;
    const unsigned short* Bl = (layer == 0) ? g_w1lo : g_w2lo;

    float acc[2][8][4];
#pragma unroll
    for (int i = 0; i < 2; i++)
#pragma unroll
        for (int j = 0; j < 8; j++)
#pragma unroll
            for (int c = 0; c < 4; c++) acc[i][j][c] = 0.0f;

    // loader mapping: 1024 uint4 per tile; 4 per thread
    const int l_r = tid >> 3;            // base rows tid/8 + 32*it
    const int l_c = (tid & 7) * 8;       // bf16 col group

#pragma unroll
    for (int chunk = 0; chunk < 2; chunk++) {
        const int kb = chunk * 64;
        if (chunk) __syncthreads();   // protect previous tiles before overwrite
        // load A hi/lo (guarded) and B hi/lo
#pragma unroll
        for (int it = 0; it < 4; it++) {
            int r = l_r + it * 32;
            int gr = block_row + r;
            uint4 vh = make_uint4(0u, 0u, 0u, 0u), vl = vh;
            if (gr < N_NODES) {
                vh = *reinterpret_cast<const uint4*>(Ah + (size_t)gr * D + kb + l_c);
                vl = *reinterpret_cast<const uint4*>(Al + (size_t)gr * D + kb + l_c);
            }
            int so = (r * SP + l_c) * 2;
            *reinterpret_cast<uint4*>(smem + OFF_AHI + so) = vh;
            *reinterpret_cast<uint4*>(smem + OFF_ALO + so) = vl;
            uint4 wh = *reinterpret_cast<const uint4*>(Bh + (size_t)r * D + kb + l_c);
            uint4 wl = *reinterpret_cast<const uint4*>(Bl + (size_t)r * D + kb + l_c);
            *reinterpret_cast<uint4*>(smem + OFF_BHI + so) = wh;
            *reinterpret_cast<uint4*>(smem + OFF_BLO + so) = wl;
        }
        __syncthreads();

#pragma unroll
        for (int k16 = 0; k16 < 4; k16++) {
            const int k0 = k16 * 16;
            uint32_t ahi[2][4], alo[2][4];
#pragma unroll
            for (int mi = 0; mi < 2; mi++) {
                int arow = m0 + mi * 16 + ((g & 1) << 3) + lane8;
                int acol = k0 + ((g >> 1) << 3);
                uint32_t ao = (uint32_t)(arow * SP + acol) * 2;
                ldsm4(ahi[mi], sb + OFF_AHI + ao);
                ldsm4(alo[mi], sb + OFF_ALO + ao);
            }
#pragma unroll
            for (int jj = 0; jj < 4; jj++) {
                int brow = n0 + jj * 16 + ((g >> 1) << 3) + lane8;
                int bcol = k0 + ((g & 1) << 3);
                uint32_t bo = (uint32_t)(brow * SP + bcol) * 2;
                uint32_t bh[4], bl[4];
                ldsm4(bh, sb + OFF_BHI + bo);
                ldsm4(bl, sb + OFF_BLO + bo);
#pragma unroll
                for (int f = 0; f < 2; f++) {
                    uint32_t bh0 = bh[2 * f], bh1 = bh[2 * f + 1];
                    uint32_t bl0 = bl[2 * f], bl1 = bl[2 * f + 1];
#pragma unroll
                    for (int mi = 0; mi < 2; mi++) {
                        float* d = acc[mi][jj * 2 + f];
                        mma16816(d, ahi[mi], bh0, bh1);   // hi*hi
                        mma16816(d, ahi[mi], bl0, bl1);   // hi*lo
                        mma16816(d, alo[mi], bh0, bh1);   // lo*hi
                    }
                }
            }
        }
    }

    // epilogue: write fp32 to g_h
#pragma unroll
    for (int mi = 0; mi < 2; mi++) {
#pragma unroll
        for (int j = 0; j < 8; j++) {
            int row = block_row + m0 + mi * 16 + (lane >> 2);
            int col = n0 + j * 8 + (lane & 3) * 2;
            float* d = acc[mi][j];
            if (row < N_NODES)
                *reinterpret_cast<float2*>((float*)g_h + (size_t)row * D + col) = make_float2(d[0], d[1]);
            if (row + 8 < N_NODES)
                *reinterpret_cast<float2*>((float*)g_h + (size_t)(row + 8) * D + col) = make_float2(d[2], d[3]);
        }
    }
}

// ---------------- aggregate: relu( sum_{e in CSR[n]} g_h[src_e]*scale_e + bias ) ----------------
// layer 0 -> writes bf16 hi/lo split (g_yhi/g_ylo); layer 1 -> writes fp32 out_ext.
__global__ __launch_bounds__(256) void agg_kernel(const float* __restrict__ bias,
                                                  float* __restrict__ out_ext,
                                                  int layer) {
    int warp = (blockIdx.x * blockDim.x + threadIdx.x) >> 5;
    int lane = threadIdx.x & 31;
    if (warp >= N_NODES) return;
    const float* H = (const float*)g_h;
    int begin = g_rowptr[warp];
    int end   = g_rowptr[warp + 1];

    float4 acc = make_float4(0.f, 0.f, 0.f, 0.f);
    int i = begin;
    for (; i + 1 < end; i += 2) {
        int   s0 = g_srcs[i],     s1 = g_srcs[i + 1];
        float w0 = g_scale[i],    w1 = g_scale[i + 1];
        float4 v0 = *reinterpret_cast<const float4*>(H + (size_t)s0 * D + lane * 4);
        float4 v1 = *reinterpret_cast<const float4*>(H + (size_t)s1 * D + lane * 4);
        acc.x += w0 * v0.x; acc.y += w0 * v0.y; acc.z += w0 * v0.z; acc.w += w0 * v0.w;
        acc.x += w1 * v1.x; acc.y += w1 * v1.y; acc.z += w1 * v1.z; acc.w += w1 * v1.w;
    }
    if (i < end) {
        int   s0 = g_srcs[i];
        float w0 = g_scale[i];
        float4 v0 = *reinterpret_cast<const float4*>(H + (size_t)s0 * D + lane * 4);
        acc.x += w0 * v0.x; acc.y += w0 * v0.y; acc.z += w0 * v0.z; acc.w += w0 * v0.w;
    }

    float4 b = *reinterpret_cast<const float4*>(bias + lane * 4);
    float4 r;
    r.x = acc.x + b.x; r.x = r.x > 0.f ? r.x : 0.f;
    r.y = acc.y + b.y; r.y = r.y > 0.f ? r.y : 0.f;
    r.z = acc.z + b.z; r.z = r.z > 0.f ? r.z : 0.f;
    r.w = acc.w + b.w; r.w = r.w > 0.f ? r.w : 0.f;

    if (layer == 1) {
        *reinterpret_cast<float4*>(out_ext + (size_t)warp * D + lane * 4) = r;
    } else {
        ushort4 hi, lo;
        split_bf16(r.x, hi.x, lo.x); split_bf16(r.y, hi.y, lo.y);
        split_bf16(r.z, hi.z, lo.z); split_bf16(r.w, hi.w, lo.w);
        size_t idx = ((size_t)warp * D + lane * 4) >> 2;
        reinterpret_cast<ushort4*>(g_yhi)[idx] = hi;
        reinterpret_cast<ushort4*>(g_ylo)[idx] = lo;
    }
}

// ---------------- launch ----------------
extern "C" void kernel_launch(void* const* d_in, const int* in_sizes, int n_in,
                              void* d_out, int out_size) {
    const float* x  = (const float*)d_in[0];
    const void*  ei = d_in[1];                 // int32 or int64, auto-detected
    const float* ea = (const float*)d_in[2];
    const float* W1 = (const float*)d_in[3];
    const float* b1 = (const float*)d_in[4];
    const float* W2 = (const float*)d_in[5];
    const float* b2 = (const float*)d_in[6];
    float* out = (float*)d_out;

    cudaFuncSetAttribute(gemm_mma_kernel, cudaFuncAttributeMaxDynamicSharedMemorySize, GEMM_SMEM);

    const int gemm_grid = (N_NODES + 127) / 128;        // 313
    const int agg_grid  = (N_NODES * 32 + 255) / 256;   // 5000 blocks
    const int convx_grid = (N_NODES * D / 4 + 255) / 256;

    init_kernel<<<NB, 256>>>((const int*)ei);                         // 0
    conv_x_kernel<<<convx_grid, 256>>>(x);                            // 1
    conv_w_kernel<<<32, 256>>>(W1, W2);                               // 2
    gemm_mma_kernel<<<gemm_grid, 256, GEMM_SMEM>>>(0);                // 3  <- profiled slot
    count_kernel<<<(N_EDGES + 255) / 256, 256>>>(ei);                 // 4
    bsum_kernel<<<NB, 256>>>();                                       // 5
    bscan_kernel<<<1, 256>>>();                                       // 6
    rowptr_kernel<<<NB, 256>>>();                                     // 7
    fill_kernel<<<(N_EDGES + 255) / 256, 256>>>(ei, ea);              // 8
    agg_kernel<<<agg_grid, 256>>>(b1, out, 0);                        // 9
    gemm_mma_kernel<<<gemm_grid, 256, GEMM_SMEM>>>(1);                // 10
    agg_kernel<<<agg_grid, 256>>>(b2, out, 1);                        // 11
}

// round 11
// speedup vs baseline: 1.0350x; 1.0350x over previous
#include <cuda_runtime.h>
#include <cuda_bf16.h>
#include <cstdint>

#define N_NODES 40000
#define N_EDGES 640000
#define D 128
#define NB 157  // ceil(40000/256) scan blocks

// ---------------- scratch (device globals, referenced by symbol only) ----------------
__device__ float g_h[N_NODES * D];            // GEMM output (per layer), fp32
__device__ unsigned short g_xhi[N_NODES * D]; // bf16 split of x
__device__ unsigned short g_xlo[N_NODES * D];
__device__ unsigned short g_yhi[N_NODES * D]; // bf16 split of layer-1 output
__device__ unsigned short g_ylo[N_NODES * D];
__device__ unsigned short g_w1hi[D * D], g_w1lo[D * D];
__device__ unsigned short g_w2hi[D * D], g_w2lo[D * D];
__device__ int   g_deg[N_NODES];
__device__ int   g_rowptr[N_NODES + 1];
__device__ int   g_cursor[N_NODES];
__device__ int   g_srcs[N_EDGES];
__device__ float g_scale[N_EDGES];
__device__ int   g_is32;
__device__ int   g_bsum[NB];
__device__ int   g_boff[NB];

// ---------------- init: zero degree histogram + detect edge_index dtype ----------------
__global__ __launch_bounds__(256) void init_kernel(const int* __restrict__ ei32) {
    int i = blockIdx.x * 256 + threadIdx.x;
    if (i < N_NODES) g_deg[i] = 0;
    if (blockIdx.x == 0) {
        int nz = 0;
        for (int s = threadIdx.x; s < 4096; s += 256)
            nz |= (ei32[2 * s + 1] != 0);
        nz = __syncthreads_or(nz);
        if (threadIdx.x == 0) g_is32 = nz;
    }
}

__device__ __forceinline__ int load_idx(const void* ei, int pos) {
    if (g_is32) return ((const int*)ei)[pos];
    return (int)((const long long*)ei)[pos];
}

__global__ void count_kernel(const void* __restrict__ ei) {
    int e = blockIdx.x * blockDim.x + threadIdx.x;
    if (e >= N_EDGES) return;
    int dst = load_idx(ei, N_EDGES + e);
    if ((unsigned)dst < (unsigned)N_NODES) atomicAdd(&g_deg[dst], 1);
}

__global__ __launch_bounds__(256) void bsum_kernel() {
    int i = blockIdx.x * 256 + threadIdx.x;
    int v = (i < N_NODES) ? g_deg[i] : 0;
#pragma unroll
    for (int off = 16; off > 0; off >>= 1)
        v += __shfl_down_sync(0xffffffffu, v, off);
    __shared__ int ws[8];
    int wid = threadIdx.x >> 5, lane = threadIdx.x & 31;
    if (lane == 0) ws[wid] = v;
    __syncthreads();
    if (threadIdx.x == 0) {
        int s = 0;
#pragma unroll
        for (int w = 0; w < 8; w++) s += ws[w];
        g_bsum[blockIdx.x] = s;
    }
}

__global__ __launch_bounds__(256) void bscan_kernel() {
    int t = threadIdx.x;
    int lane = t & 31, wid = t >> 5;
    int v = (t < NB) ? g_bsum[t] : 0;
    int orig = v;
#pragma unroll
    for (int off = 1; off < 32; off <<= 1) {
        int u = __shfl_up_sync(0xffffffffu, v, off);
        if (lane >= off) v += u;
    }
    __shared__ int wsum[8];
    if (lane == 31) wsum[wid] = v;
    __syncthreads();
    if (wid == 0) {
        int s = (lane < 8) ? wsum[lane] : 0;
#pragma unroll
        for (int off = 1; off < 8; off <<= 1) {
            int u = __shfl_up_sync(0xffffffffu, s, off);
            if (lane >= off) s += u;
        }
        if (lane < 8) wsum[lane] = s;
    }
    __syncthreads();
    int incl = v + (wid > 0 ? wsum[wid - 1] : 0);
    if (t < NB) g_boff[t] = incl - orig;
}

__global__ __launch_bounds__(256) void rowptr_kernel() {
    int i = blockIdx.x * 256 + threadIdx.x;
    int lane = threadIdx.x & 31, wid = threadIdx.x >> 5;
    int v = (i < N_NODES) ? g_deg[i] : 0;
    int orig = v;
#pragma unroll
    for (int off = 1; off < 32; off <<= 1) {
        int u = __shfl_up_sync(0xffffffffu, v, off);
        if (lane >= off) v += u;
    }
    __shared__ int wsum[8];
    if (lane == 31) wsum[wid] = v;
    __syncthreads();
    if (wid == 0) {
        int s = (lane < 8) ? wsum[lane] : 0;
#pragma unroll
        for (int off = 1; off < 8; off <<= 1) {
            int u = __shfl_up_sync(0xffffffffu, s, off);
            if (lane >= off) s += u;
        }
        if (lane < 8) wsum[lane] = s;
    }
    __syncthreads();
    int incl = v + (wid > 0 ? wsum[wid - 1] : 0);
    int excl = incl - orig + g_boff[blockIdx.x];
    if (i < N_NODES) {
        g_rowptr[i] = excl;
        g_cursor[i] = excl;
        if (i == N_NODES - 1) g_rowptr[N_NODES] = excl + orig;
    }
}

__global__ void fill_kernel(const void* __restrict__ ei,
                            const float* __restrict__ ea) {
    int e = blockIdx.x * blockDim.x + threadIdx.x;
    if (e >= N_EDGES) return;
    int src = load_idx(ei, e);
    int dst = load_idx(ei, N_EDGES + e);
    if ((unsigned)dst >= (unsigned)N_NODES) return;
    if ((unsigned)src >= (unsigned)N_NODES) return;
    int pos = atomicAdd(&g_cursor[dst], 1);
    g_srcs[pos]  = src;
    g_scale[pos] = 1.0f / ea[e];
}

// ---------------- f32 -> bf16 hi/lo split converters ----------------
__device__ __forceinline__ void split_bf16(float f, unsigned short& hi, unsigned short& lo) {
    __nv_bfloat16 h = __float2bfloat16(f);
    float r = f - __bfloat162float(h);
    hi = __bfloat16_as_ushort(h);
    lo = __bfloat16_as_ushort(__float2bfloat16(r));
}

__global__ __launch_bounds__(256) void conv_x_kernel(const float* __restrict__ x) {
    int i = blockIdx.x * 256 + threadIdx.x;      // float4 index
    if (i * 4 >= N_NODES * D) return;
    float4 v = reinterpret_cast<const float4*>(x)[i];
    ushort4 hi, lo;
    split_bf16(v.x, hi.x, lo.x); split_bf16(v.y, hi.y, lo.y);
    split_bf16(v.z, hi.z, lo.z); split_bf16(v.w, hi.w, lo.w);
    reinterpret_cast<ushort4*>(g_xhi)[i] = hi;
    reinterpret_cast<ushort4*>(g_xlo)[i] = lo;
}

__global__ __launch_bounds__(256) void conv_w_kernel(const float* __restrict__ W1,
                                                     const float* __restrict__ W2) {
    int i = blockIdx.x * 256 + threadIdx.x;      // 0..8191 (two 4096 float4 sets)
    if (i >= 8192) return;
    const float* src = (i < 4096) ? W1 : W2;
    unsigned short* dh = (i < 4096) ? g_w1hi : g_w2hi;
    unsigned short* dl = (i < 4096) ? g_w1lo : g_w2lo;
    int j = i & 4095;
    float4 v = reinterpret_cast<const float4*>(src)[j];
    ushort4 hi, lo;
    split_bf16(v.x, hi.x, lo.x); split_bf16(v.y, hi.y, lo.y);
    split_bf16(v.z, hi.z, lo.z); split_bf16(v.w, hi.w, lo.w);
    reinterpret_cast<ushort4*>(dh)[j] = hi;
    reinterpret_cast<ushort4*>(dl)[j] = lo;
}

// ---------------- tensor-core GEMM via mma.sync (HMMA bf16, 3-term split) ----------------
// CTA: 64x128 tile (grid 625 = 40000/64, no row guards), 8 warps (2m x 4n),
// warp tile 32x32. K=128 in two 64-chunks. smem padded SP=72, conflict-free ldmatrix.
#define SP 72                          // padded row stride (bf16 elems)
#define A_TILE_B (64 * SP * 2)         // 9216 bytes
#define B_TILE_B (128 * SP * 2)        // 18432 bytes
#define OFF_AHI 0
#define OFF_ALO (A_TILE_B)
#define OFF_BHI (2 * A_TILE_B)
#define OFF_BLO (2 * A_TILE_B + B_TILE_B)
#define GEMM_SMEM (2 * A_TILE_B + 2 * B_TILE_B)   // 55296

__device__ __forceinline__ void ldsm4(uint32_t* r, uint32_t addr) {
    asm volatile("ldmatrix.sync.aligned.m8n8.x4.shared.b16 {%0,%1,%2,%3}, [%4];"
                 : "=r"(r[0]), "=r"(r[1]), "=r"(r[2]), "=r"(r[3]) : "r"(addr));
}
__device__ __forceinline__ void mma16816(float* d, const uint32_t* a, uint32_t b0, uint32_t b1) {
    asm volatile(
        "mma.sync.aligned.m16n8k16.row.col.f32.bf16.bf16.f32 "
        "{%0,%1,%2,%3}, {%4,%5,%6,%7}, {%8,%9}, {%0,%1,%2,%3};"
        : "+f"(d[0]), "+f"(d[1]), "+f"(d[2]), "+f"(d[3])
        : "r"(a[0]), "r"(a[1]), "r"(a[2]), "r"(a[3]), "r"(b0), "r"(b1));
}

__global__ __launch_bounds__(256, 3) void gemm_mma_kernel(int layer) {
    extern __shared__ char smem[];
    uint32_t sb;
    asm("{ .reg .u64 t; cvta.to.shared.u64 t, %1; cvt.u32.u64 %0, t; }" : "=r"(sb) : "l"(smem));
    const int tid  = threadIdx.x;
    const int wid  = tid >> 5;
    const int lane = tid & 31;
    const int lane8 = lane & 7;
    const int g     = lane >> 3;
    const int m0 = (wid & 1) * 32;       // 2 m-groups of 32 rows
    const int n0 = (wid >> 1) * 32;      // 4 n-groups of 32 cols
    const int block_row = blockIdx.x * 64;

    const unsigned short* Ah = (layer == 0) ? g_xhi : g_yhi;
    const unsigned short* Al = (layer == 0) ? g_xlo : g_ylo;
    const unsigned short* Bh = (layer == 0) ? g_w1hi : g_w2hi;
    const unsigned short* Bl = (layer == 0) ? g_w1lo : g_w2lo;

    float acc[2][4][4];
#pragma unroll
    for (int i = 0; i < 2; i++)
#pragma unroll
        for (int j = 0; j < 4; j++)
#pragma unroll
            for (int c = 0; c < 4; c++) acc[i][j][c] = 0.0f;

#pragma unroll
    for (int chunk = 0; chunk < 2; chunk++) {
        const int kb = chunk * 64;
        if (chunk) __syncthreads();   // protect previous tiles before overwrite

        // A tiles: 64 rows x 64 k-bf16 = 512 uint4; 2 per thread
#pragma unroll
        for (int it = 0; it < 2; it++) {
            int idx = tid + it * 256;
            int r = idx >> 3;             // 0..63
            int c = (idx & 7) * 8;        // bf16 col within chunk
            int gr = block_row + r;
            uint4 vh = *reinterpret_cast<const uint4*>(Ah + (size_t)gr * D + kb + c);
            uint4 vl = *reinterpret_cast<const uint4*>(Al + (size_t)gr * D + kb + c);
            int so = (r * SP + c) * 2;
            *reinterpret_cast<uint4*>(smem + OFF_AHI + so) = vh;
            *reinterpret_cast<uint4*>(smem + OFF_ALO + so) = vl;
        }
        // B tiles: 128 n-rows x 64 k-bf16 = 1024 uint4; 4 per thread
#pragma unroll
        for (int it = 0; it < 4; it++) {
            int idx = tid + it * 256;
            int r = idx >> 3;             // 0..127
            int c = (idx & 7) * 8;
            uint4 wh = *reinterpret_cast<const uint4*>(Bh + (size_t)r * D + kb + c);
            uint4 wl = *reinterpret_cast<const uint4*>(Bl + (size_t)r * D + kb + c);
            int so = (r * SP + c) * 2;
            *reinterpret_cast<uint4*>(smem + OFF_BHI + so) = wh;
            *reinterpret_cast<uint4*>(smem + OFF_BLO + so) = wl;
        }
        __syncthreads();

#pragma unroll
        for (int k16 = 0; k16 < 4; k16++) {
            const int k0 = k16 * 16;
            uint32_t ahi[2][4], alo[2][4];
#pragma unroll
            for (int mi = 0; mi < 2; mi++) {
                int arow = m0 + mi * 16 + ((g & 1) << 3) + lane8;
                int acol = k0 + ((g >> 1) << 3);
                uint32_t ao = (uint32_t)(arow * SP + acol) * 2;
                ldsm4(ahi[mi], sb + OFF_AHI + ao);
                ldsm4(alo[mi], sb + OFF_ALO + ao);
            }
#pragma unroll
            for (int jj = 0; jj < 2; jj++) {
                int brow = n0 + jj * 16 + ((g >> 1) << 3) + lane8;
                int bcol = k0 + ((g & 1) << 3);
                uint32_t bo = (uint32_t)(brow * SP + bcol) * 2;
                uint32_t bh[4], bl[4];
                ldsm4(bh, sb + OFF_BHI + bo);
                ldsm4(bl, sb + OFF_BLO + bo);
#pragma unroll
                for (int f = 0; f < 2; f++) {
                    uint32_t bh0 = bh[2 * f], bh1 = bh[2 * f + 1];
                    uint32_t bl0 = bl[2 * f], bl1 = bl[2 * f + 1];
#pragma unroll
                    for (int mi = 0; mi < 2; mi++) {
                        float* d = acc[mi][jj * 2 + f];
                        mma16816(d, ahi[mi], bh0, bh1);   // hi*hi
                        mma16816(d, ahi[mi], bl0, bl1);   // hi*lo
                        mma16816(d, alo[mi], bh0, bh1);   // lo*hi
                    }
                }
            }
        }
    }

    // epilogue: write fp32 to g_h (no guards: 40000 % 64 == 0)
#pragma unroll
    for (int mi = 0; mi < 2; mi++) {
#pragma unroll
        for (int j = 0; j < 4; j++) {
            int row = block_row + m0 + mi * 16 + (lane >> 2);
            int col = n0 + j * 8 + (lane & 3) * 2;
            float* d = acc[mi][j];
            *reinterpret_cast<float2*>((float*)g_h + (size_t)row * D + col) = make_float2(d[0], d[1]);
            *reinterpret_cast<float2*>((float*)g_h + (size_t)(row + 8) * D + col) = make_float2(d[2], d[3]);
        }
    }
}

// ---------------- aggregate: relu( sum_{e in CSR[n]} g_h[src_e]*scale_e + bias ) ----------------
// layer 0 -> writes bf16 hi/lo split (g_yhi/g_ylo); layer 1 -> writes fp32 out_ext.
__global__ __launch_bounds__(256) void agg_kernel(const float* __restrict__ bias,
                                                  float* __restrict__ out_ext,
                                                  int layer) {
    int warp = (blockIdx.x * blockDim.x + threadIdx.x) >> 5;
    int lane = threadIdx.x & 31;
    if (warp >= N_NODES) return;
    const float* H = (const float*)g_h;
    int begin = g_rowptr[warp];
    int end   = g_rowptr[warp + 1];

    float4 acc = make_float4(0.f, 0.f, 0.f, 0.f);
    int i = begin;
    for (; i + 1 < end; i += 2) {
        int   s0 = g_srcs[i],     s1 = g_srcs[i + 1];
        float w0 = g_scale[i],    w1 = g_scale[i + 1];
        float4 v0 = *reinterpret_cast<const float4*>(H + (size_t)s0 * D + lane * 4);
        float4 v1 = *reinterpret_cast<const float4*>(H + (size_t)s1 * D + lane * 4);
        acc.x += w0 * v0.x; acc.y += w0 * v0.y; acc.z += w0 * v0.z; acc.w += w0 * v0.w;
        acc.x += w1 * v1.x; acc.y += w1 * v1.y; acc.z += w1 * v1.z; acc.w += w1 * v1.w;
    }
    if (i < end) {
        int   s0 = g_srcs[i];
        float w0 = g_scale[i];
        float4 v0 = *reinterpret_cast<const float4*>(H + (size_t)s0 * D + lane * 4);
        acc.x += w0 * v0.x; acc.y += w0 * v0.y; acc.z += w0 * v0.z; acc.w += w0 * v0.w;
    }

    float4 b = *reinterpret_cast<const float4*>(bias + lane * 4);
    float4 r;
    r.x = acc.x + b.x; r.x = r.x > 0.f ? r.x : 0.f;
    r.y = acc.y + b.y; r.y = r.y > 0.f ? r.y : 0.f;
    r.z = acc.z + b.z; r.z = r.z > 0.f ? r.z : 0.f;
    r.w = acc.w + b.w; r.w = r.w > 0.f ? r.w : 0.f;

    if (layer == 1) {
        *reinterpret_cast<float4*>(out_ext + (size_t)warp * D + lane * 4) = r;
    } else {
        ushort4 hi, lo;
        split_bf16(r.x, hi.x, lo.x); split_bf16(r.y, hi.y, lo.y);
        split_bf16(r.z, hi.z, lo.z); split_bf16(r.w, hi.w, lo.w);
        size_t idx = ((size_t)warp * D + lane * 4) >> 2;
        reinterpret_cast<ushort4*>(g_yhi)[idx] = hi;
        reinterpret_cast<ushort4*>(g_ylo)[idx] = lo;
    }
}

// ---------------- launch ----------------
extern "C" void kernel_launch(void* const* d_in, const int* in_sizes, int n_in,
                              void* d_out, int out_size) {
    const float* x  = (const float*)d_in[0];
    const void*  ei = d_in[1];                 // int32 or int64, auto-detected
    const float* ea = (const float*)d_in[2];
    const float* W1 = (const float*)d_in[3];
    const float* b1 = (const float*)d_in[4];
    const float* W2 = (const float*)d_in[5];
    const float* b2 = (const float*)d_in[6];
    float* out = (float*)d_out;

    cudaFuncSetAttribute(gemm_mma_kernel, cudaFuncAttributeMaxDynamicSharedMemorySize, GEMM_SMEM);

    const int gemm_grid = N_NODES / 64;                 // 625, exact
    const int agg_grid  = (N_NODES * 32 + 255) / 256;   // 5000 blocks
    const int convx_grid = (N_NODES * D / 4 + 255) / 256;

    init_kernel<<<NB, 256>>>((const int*)ei);                         // 0
    conv_x_kernel<<<convx_grid, 256>>>(x);                            // 1
    conv_w_kernel<<<32, 256>>>(W1, W2);                               // 2
    gemm_mma_kernel<<<gemm_grid, 256, GEMM_SMEM>>>(0);                // 3  <- profiled slot
    count_kernel<<<(N_EDGES + 255) / 256, 256>>>(ei);                 // 4
    bsum_kernel<<<NB, 256>>>();                                       // 5
    bscan_kernel<<<1, 256>>>();                                       // 6
    rowptr_kernel<<<NB, 256>>>();                                     // 7
    fill_kernel<<<(N_EDGES + 255) / 256, 256>>>(ei, ea);              // 8
    agg_kernel<<<agg_grid, 256>>>(b1, out, 0);                        // 9
    gemm_mma_kernel<<<gemm_grid, 256, GEMM_SMEM>>>(1);                // 10
    agg_kernel<<<agg_grid, 256>>>(b2, out, 1);                        // 11
}

// round 12
// speedup vs baseline: 1.0699x; 1.0338x over previous
#include <cuda_runtime.h>
#include <cuda_bf16.h>
#include <cstdint>

#define N_NODES 40000
#define N_EDGES 640000
#define D 128
#define NB 157  // ceil(40000/256) scan blocks

// ---------------- scratch (device globals, referenced by symbol only) ----------------
__device__ float g_h[N_NODES * D];            // GEMM output (per layer), fp32
__device__ unsigned short g_xhi[N_NODES * D]; // bf16 split of x
__device__ unsigned short g_xlo[N_NODES * D];
__device__ unsigned short g_yhi[N_NODES * D]; // bf16 split of layer-1 output
__device__ unsigned short g_ylo[N_NODES * D];
__device__ unsigned short g_w1hi[D * D], g_w1lo[D * D];
__device__ unsigned short g_w2hi[D * D], g_w2lo[D * D];
__device__ int   g_deg[N_NODES];
__device__ int   g_rowptr[N_NODES + 1];
__device__ int   g_cursor[N_NODES];
__device__ int   g_srcs[N_EDGES];
__device__ float g_scale[N_EDGES];
__device__ int   g_is32;
__device__ int   g_bsum[NB];
__device__ int   g_boff[NB];

// ---------------- init: zero degree histogram + detect edge_index dtype ----------------
__global__ __launch_bounds__(256) void init_kernel(const int* __restrict__ ei32) {
    int i = blockIdx.x * 256 + threadIdx.x;
    if (i < N_NODES) g_deg[i] = 0;
    if (blockIdx.x == 0) {
        int nz = 0;
        for (int s = threadIdx.x; s < 4096; s += 256)
            nz |= (ei32[2 * s + 1] != 0);
        nz = __syncthreads_or(nz);
        if (threadIdx.x == 0) g_is32 = nz;
    }
}

__device__ __forceinline__ int load_idx(const void* ei, int pos) {
    if (g_is32) return ((const int*)ei)[pos];
    return (int)((const long long*)ei)[pos];
}

__global__ void count_kernel(const void* __restrict__ ei) {
    int e = blockIdx.x * blockDim.x + threadIdx.x;
    if (e >= N_EDGES) return;
    int dst = load_idx(ei, N_EDGES + e);
    if ((unsigned)dst < (unsigned)N_NODES) atomicAdd(&g_deg[dst], 1);
}

__global__ __launch_bounds__(256) void bsum_kernel() {
    int i = blockIdx.x * 256 + threadIdx.x;
    int v = (i < N_NODES) ? g_deg[i] : 0;
#pragma unroll
    for (int off = 16; off > 0; off >>= 1)
        v += __shfl_down_sync(0xffffffffu, v, off);
    __shared__ int ws[8];
    int wid = threadIdx.x >> 5, lane = threadIdx.x & 31;
    if (lane == 0) ws[wid] = v;
    __syncthreads();
    if (threadIdx.x == 0) {
        int s = 0;
#pragma unroll
        for (int w = 0; w < 8; w++) s += ws[w];
        g_bsum[blockIdx.x] = s;
    }
}

__global__ __launch_bounds__(256) void bscan_kernel() {
    int t = threadIdx.x;
    int lane = t & 31, wid = t >> 5;
    int v = (t < NB) ? g_bsum[t] : 0;
    int orig = v;
#pragma unroll
    for (int off = 1; off < 32; off <<= 1) {
        int u = __shfl_up_sync(0xffffffffu, v, off);
        if (lane >= off) v += u;
    }
    __shared__ int wsum[8];
    if (lane == 31) wsum[wid] = v;
    __syncthreads();
    if (wid == 0) {
        int s = (lane < 8) ? wsum[lane] : 0;
#pragma unroll
        for (int off = 1; off < 8; off <<= 1) {
            int u = __shfl_up_sync(0xffffffffu, s, off);
            if (lane >= off) s += u;
        }
        if (lane < 8) wsum[lane] = s;
    }
    __syncthreads();
    int incl = v + (wid > 0 ? wsum[wid - 1] : 0);
    if (t < NB) g_boff[t] = incl - orig;
}

__global__ __launch_bounds__(256) void rowptr_kernel() {
    int i = blockIdx.x * 256 + threadIdx.x;
    int lane = threadIdx.x & 31, wid = threadIdx.x >> 5;
    int v = (i < N_NODES) ? g_deg[i] : 0;
    int orig = v;
#pragma unroll
    for (int off = 1; off < 32; off <<= 1) {
        int u = __shfl_up_sync(0xffffffffu, v, off);
        if (lane >= off) v += u;
    }
    __shared__ int wsum[8];
    if (lane == 31) wsum[wid] = v;
    __syncthreads();
    if (wid == 0) {
        int s = (lane < 8) ? wsum[lane] : 0;
#pragma unroll
        for (int off = 1; off < 8; off <<= 1) {
            int u = __shfl_up_sync(0xffffffffu, s, off);
            if (lane >= off) s += u;
        }
        if (lane < 8) wsum[lane] = s;
    }
    __syncthreads();
    int incl = v + (wid > 0 ? wsum[wid - 1] : 0);
    int excl = incl - orig + g_boff[blockIdx.x];
    if (i < N_NODES) {
        g_rowptr[i] = excl;
        g_cursor[i] = excl;
        if (i == N_NODES - 1) g_rowptr[N_NODES] = excl + orig;
    }
}

__global__ void fill_kernel(const void* __restrict__ ei,
                            const float* __restrict__ ea) {
    int e = blockIdx.x * blockDim.x + threadIdx.x;
    if (e >= N_EDGES) return;
    int src = load_idx(ei, e);
    int dst = load_idx(ei, N_EDGES + e);
    if ((unsigned)dst >= (unsigned)N_NODES) return;
    if ((unsigned)src >= (unsigned)N_NODES) return;
    int pos = atomicAdd(&g_cursor[dst], 1);
    g_srcs[pos]  = src;
    g_scale[pos] = 1.0f / ea[e];
}

// ---------------- f32 -> bf16 hi/lo split converters ----------------
__device__ __forceinline__ void split_bf16(float f, unsigned short& hi, unsigned short& lo) {
    __nv_bfloat16 h = __float2bfloat16(f);
    float r = f - __bfloat162float(h);
    hi = __bfloat16_as_ushort(h);
    lo = __bfloat16_as_ushort(__float2bfloat16(r));
}

__global__ __launch_bounds__(256) void conv_x_kernel(const float* __restrict__ x) {
    int i = blockIdx.x * 256 + threadIdx.x;      // float4 index
    if (i * 4 >= N_NODES * D) return;
    float4 v = reinterpret_cast<const float4*>(x)[i];
    ushort4 hi, lo;
    split_bf16(v.x, hi.x, lo.x); split_bf16(v.y, hi.y, lo.y);
    split_bf16(v.z, hi.z, lo.z); split_bf16(v.w, hi.w, lo.w);
    reinterpret_cast<ushort4*>(g_xhi)[i] = hi;
    reinterpret_cast<ushort4*>(g_xlo)[i] = lo;
}

__global__ __launch_bounds__(256) void conv_w_kernel(const float* __restrict__ W1,
                                                     const float* __restrict__ W2) {
    int i = blockIdx.x * 256 + threadIdx.x;      // 0..8191 (two 4096 float4 sets)
    if (i >= 8192) return;
    const float* src = (i < 4096) ? W1 : W2;
    unsigned short* dh = (i < 4096) ? g_w1hi : g_w2hi;
    unsigned short* dl = (i < 4096) ? g_w1lo : g_w2lo;
    int j = i & 4095;
    float4 v = reinterpret_cast<const float4*>(src)[j];
    ushort4 hi, lo;
    split_bf16(v.x, hi.x, lo.x); split_bf16(v.y, hi.y, lo.y);
    split_bf16(v.z, hi.z, lo.z); split_bf16(v.w, hi.w, lo.w);
    reinterpret_cast<ushort4*>(dh)[j] = hi;
    reinterpret_cast<ushort4*>(dl)[j] = lo;
}

// ---------------- tensor-core GEMM via mma.sync (HMMA bf16, 3-term split) ----------------
// CTA: 64x128 tile (grid 625, no guards), 8 warps (2m x 4n), warp tile 32x32.
// Single K=128 chunk, cp.async bulk prefetch, one sync. SP=136 pad (conflict-free ldmatrix).
// 104448 B smem -> 2 CTAs/SM; load/compute overlap comes from CTA interleaving.
#define SP 136                         // padded row stride (bf16 elems)
#define A_TILE_B (64 * SP * 2)         // 17408 bytes
#define B_TILE_B (128 * SP * 2)        // 34816 bytes
#define OFF_AHI 0
#define OFF_ALO (A_TILE_B)
#define OFF_BHI (2 * A_TILE_B)
#define OFF_BLO (2 * A_TILE_B + B_TILE_B)
#define GEMM_SMEM (2 * A_TILE_B + 2 * B_TILE_B)   // 104448

__device__ __forceinline__ void ldsm4(uint32_t* r, uint32_t addr) {
    asm volatile("ldmatrix.sync.aligned.m8n8.x4.shared.b16 {%0,%1,%2,%3}, [%4];"
                 : "=r"(r[0]), "=r"(r[1]), "=r"(r[2]), "=r"(r[3]) : "r"(addr));
}
__device__ __forceinline__ void mma16816(float* d, const uint32_t* a, uint32_t b0, uint32_t b1) {
    asm volatile(
        "mma.sync.aligned.m16n8k16.row.col.f32.bf16.bf16.f32 "
        "{%0,%1,%2,%3}, {%4,%5,%6,%7}, {%8,%9}, {%0,%1,%2,%3};"
        : "+f"(d[0]), "+f"(d[1]), "+f"(d[2]), "+f"(d[3])
        : "r"(a[0]), "r"(a[1]), "r"(a[2]), "r"(a[3]), "r"(b0), "r"(b1));
}
__device__ __forceinline__ void cp16(uint32_t saddr, const void* gptr) {
    asm volatile("cp.async.cg.shared.global [%0], [%1], 16;" :: "r"(saddr), "l"(gptr));
}

__global__ __launch_bounds__(256, 2) void gemm_mma_kernel(int layer) {
    extern __shared__ char smem[];
    uint32_t sb;
    asm("{ .reg .u64 t; cvta.to.shared.u64 t, %1; cvt.u32.u64 %0, t; }" : "=r"(sb) : "l"(smem));
    const int tid  = threadIdx.x;
    const int wid  = tid >> 5;
    const int lane = tid & 31;
    const int lane8 = lane & 7;
    const int g     = lane >> 3;
    const int m0 = (wid & 1) * 32;       // 2 m-groups of 32 rows
    const int n0 = (wid >> 1) * 32;      // 4 n-groups of 32 cols
    const int block_row = blockIdx.x * 64;

    const unsigned short* Ah = (layer == 0) ? g_xhi : g_yhi;
    const unsigned short* Al = (layer == 0) ? g_xlo : g_ylo;
    const unsigned short* Bh = (layer == 0) ? g_w1hi : g_w2hi;
    const unsigned short* Bl = (layer == 0) ? g_w1lo : g_w2lo;

    // ---- issue all tile loads via cp.async (max MLP, zero register staging) ----
    // A tiles: 64 rows x 128 cols bf16 = 1024 uint4 each; 4 per thread
#pragma unroll
    for (int it = 0; it < 4; it++) {
        int idx = tid + it * 256;
        int r = idx >> 4;                // 0..63
        int c = (idx & 15) * 8;          // 0..120
        int gr = block_row + r;
        uint32_t so = (uint32_t)(r * SP + c) * 2;
        cp16(sb + OFF_AHI + so, Ah + (size_t)gr * D + c);
        cp16(sb + OFF_ALO + so, Al + (size_t)gr * D + c);
    }
    // B tiles: 128 rows x 128 cols bf16 = 2048 uint4 each; 8 per thread
#pragma unroll
    for (int it = 0; it < 8; it++) {
        int idx = tid + it * 256;
        int r = idx >> 4;                // 0..127
        int c = (idx & 15) * 8;
        uint32_t so = (uint32_t)(r * SP + c) * 2;
        cp16(sb + OFF_BHI + so, Bh + (size_t)r * D + c);
        cp16(sb + OFF_BLO + so, Bl + (size_t)r * D + c);
    }
    asm volatile("cp.async.commit_group;" ::: "memory");

    float acc[2][4][4];
#pragma unroll
    for (int i = 0; i < 2; i++)
#pragma unroll
        for (int j = 0; j < 4; j++)
#pragma unroll
            for (int c = 0; c < 4; c++) acc[i][j][c] = 0.0f;

    asm volatile("cp.async.wait_group 0;" ::: "memory");
    __syncthreads();

#pragma unroll
    for (int k16 = 0; k16 < 8; k16++) {
        const int k0 = k16 * 16;
        uint32_t ahi[2][4], alo[2][4];
#pragma unroll
        for (int mi = 0; mi < 2; mi++) {
            int arow = m0 + mi * 16 + ((g & 1) << 3) + lane8;
            int acol = k0 + ((g >> 1) << 3);
            uint32_t ao = (uint32_t)(arow * SP + acol) * 2;
            ldsm4(ahi[mi], sb + OFF_AHI + ao);
            ldsm4(alo[mi], sb + OFF_ALO + ao);
        }
#pragma unroll
        for (int jj = 0; jj < 2; jj++) {
            int brow = n0 + jj * 16 + ((g >> 1) << 3) + lane8;
            int bcol = k0 + ((g & 1) << 3);
            uint32_t bo = (uint32_t)(brow * SP + bcol) * 2;
            uint32_t bh[4], bl[4];
            ldsm4(bh, sb + OFF_BHI + bo);
            ldsm4(bl, sb + OFF_BLO + bo);
#pragma unroll
            for (int f = 0; f < 2; f++) {
                uint32_t bh0 = bh[2 * f], bh1 = bh[2 * f + 1];
                uint32_t bl0 = bl[2 * f], bl1 = bl[2 * f + 1];
#pragma unroll
                for (int mi = 0; mi < 2; mi++) {
                    float* d = acc[mi][jj * 2 + f];
                    mma16816(d, ahi[mi], bh0, bh1);   // hi*hi
                    mma16816(d, ahi[mi], bl0, bl1);   // hi*lo
                    mma16816(d, alo[mi], bh0, bh1);   // lo*hi
                }
            }
        }
    }

    // epilogue: write fp32 to g_h (no guards: 40000 % 64 == 0)
#pragma unroll
    for (int mi = 0; mi < 2; mi++) {
#pragma unroll
        for (int j = 0; j < 4; j++) {
            int row = block_row + m0 + mi * 16 + (lane >> 2);
            int col = n0 + j * 8 + (lane & 3) * 2;
            float* d = acc[mi][j];
            *reinterpret_cast<float2*>((float*)g_h + (size_t)row * D + col) = make_float2(d[0], d[1]);
            *reinterpret_cast<float2*>((float*)g_h + (size_t)(row + 8) * D + col) = make_float2(d[2], d[3]);
        }
    }
}

// ---------------- aggregate: relu( sum_{e in CSR[n]} g_h[src_e]*scale_e + bias ) ----------------
// layer 0 -> writes bf16 hi/lo split (g_yhi/g_ylo); layer 1 -> writes fp32 out_ext.
__global__ __launch_bounds__(256) void agg_kernel(const float* __restrict__ bias,
                                                  float* __restrict__ out_ext,
                                                  int layer) {
    int warp = (blockIdx.x * blockDim.x + threadIdx.x) >> 5;
    int lane = threadIdx.x & 31;
    if (warp >= N_NODES) return;
    const float* H = (const float*)g_h;
    int begin = g_rowptr[warp];
    int end   = g_rowptr[warp + 1];

    float4 acc = make_float4(0.f, 0.f, 0.f, 0.f);
    int i = begin;
    // unroll 4 for MLP=4
    for (; i + 3 < end; i += 4) {
        int   s0 = g_srcs[i],   s1 = g_srcs[i+1], s2 = g_srcs[i+2], s3 = g_srcs[i+3];
        float w0 = g_scale[i],  w1 = g_scale[i+1], w2 = g_scale[i+2], w3 = g_scale[i+3];
        float4 v0 = *reinterpret_cast<const float4*>(H + (size_t)s0 * D + lane * 4);
        float4 v1 = *reinterpret_cast<const float4*>(H + (size_t)s1 * D + lane * 4);
        float4 v2 = *reinterpret_cast<const float4*>(H + (size_t)s2 * D + lane * 4);
        float4 v3 = *reinterpret_cast<const float4*>(H + (size_t)s3 * D + lane * 4);
        acc.x += w0 * v0.x; acc.y += w0 * v0.y; acc.z += w0 * v0.z; acc.w += w0 * v0.w;
        acc.x += w1 * v1.x; acc.y += w1 * v1.y; acc.z += w1 * v1.z; acc.w += w1 * v1.w;
        acc.x += w2 * v2.x; acc.y += w2 * v2.y; acc.z += w2 * v2.z; acc.w += w2 * v2.w;
        acc.x += w3 * v3.x; acc.y += w3 * v3.y; acc.z += w3 * v3.z; acc.w += w3 * v3.w;
    }
    for (; i < end; i++) {
        int   s0 = g_srcs[i];
        float w0 = g_scale[i];
        float4 v0 = *reinterpret_cast<const float4*>(H + (size_t)s0 * D + lane * 4);
        acc.x += w0 * v0.x; acc.y += w0 * v0.y; acc.z += w0 * v0.z; acc.w += w0 * v0.w;
    }

    float4 b = *reinterpret_cast<const float4*>(bias + lane * 4);
    float4 r;
    r.x = acc.x + b.x; r.x = r.x > 0.f ? r.x : 0.f;
    r.y = acc.y + b.y; r.y = r.y > 0.f ? r.y : 0.f;
    r.z = acc.z + b.z; r.z = r.z > 0.f ? r.z : 0.f;
    r.w = acc.w + b.w; r.w = r.w > 0.f ? r.w : 0.f;

    if (layer == 1) {
        *reinterpret_cast<float4*>(out_ext + (size_t)warp * D + lane * 4) = r;
    } else {
        ushort4 hi, lo;
        split_bf16(r.x, hi.x, lo.x); split_bf16(r.y, hi.y, lo.y);
        split_bf16(r.z, hi.z, lo.z); split_bf16(r.w, hi.w, lo.w);
        size_t idx = ((size_t)warp * D + lane * 4) >> 2;
        reinterpret_cast<ushort4*>(g_yhi)[idx] = hi;
        reinterpret_cast<ushort4*>(g_ylo)[idx] = lo;
    }
}

// ---------------- launch ----------------
extern "C" void kernel_launch(void* const* d_in, const int* in_sizes, int n_in,
                              void* d_out, int out_size) {
    const float* x  = (const float*)d_in[0];
    const void*  ei = d_in[1];                 // int32 or int64, auto-detected
    const float* ea = (const float*)d_in[2];
    const float* W1 = (const float*)d_in[3];
    const float* b1 = (const float*)d_in[4];
    const float* W2 = (const float*)d_in[5];
    const float* b2 = (const float*)d_in[6];
    float* out = (float*)d_out;

    cudaFuncSetAttribute(gemm_mma_kernel, cudaFuncAttributeMaxDynamicSharedMemorySize, GEMM_SMEM);

    const int gemm_grid = N_NODES / 64;                 // 625, exact
    const int agg_grid  = (N_NODES * 32 + 255) / 256;   // 5000 blocks
    const int convx_grid = (N_NODES * D / 4 + 255) / 256;

    init_kernel<<<NB, 256>>>((const int*)ei);                         // 0
    conv_x_kernel<<<convx_grid, 256>>>(x);                            // 1
    conv_w_kernel<<<32, 256>>>(W1, W2);                               // 2
    gemm_mma_kernel<<<gemm_grid, 256, GEMM_SMEM>>>(0);                // 3  <- profiled slot
    count_kernel<<<(N_EDGES + 255) / 256, 256>>>(ei);                 // 4
    bsum_kernel<<<NB, 256>>>();                                       // 5
    bscan_kernel<<<1, 256>>>();                                       // 6
    rowptr_kernel<<<NB, 256>>>();                                     // 7
    fill_kernel<<<(N_EDGES + 255) / 256, 256>>>(ei, ea);              // 8
    agg_kernel<<<agg_grid, 256>>>(b1, out, 0);                        // 9
    gemm_mma_kernel<<<gemm_grid, 256, GEMM_SMEM>>>(1);                // 10
    agg_kernel<<<agg_grid, 256>>>(b2, out, 1);                        // 11
}

// round 13
// speedup vs baseline: 1.1471x; 1.0721x over previous
#include <cuda_runtime.h>
#include <cuda_bf16.h>
#include <cuda_fp16.h>
#include <cstdint>

#define N_NODES 40000
#define N_EDGES 640000
#define D 128
#define NB 157  // ceil(40000/256) scan blocks

// ---------------- scratch (device globals, referenced by symbol only) ----------------
__device__ __half g_h[N_NODES * D];           // GEMM output (per layer), fp16
__device__ unsigned short g_xhi[N_NODES * D]; // bf16 split of x
__device__ unsigned short g_xlo[N_NODES * D];
__device__ unsigned short g_yhi[N_NODES * D]; // bf16 split of layer-1 output
__device__ unsigned short g_ylo[N_NODES * D];
__device__ unsigned short g_w1hi[D * D], g_w1lo[D * D];
__device__ unsigned short g_w2hi[D * D], g_w2lo[D * D];
__device__ int   g_deg[N_NODES];
__device__ int   g_rowptr[N_NODES + 1];
__device__ int   g_cursor[N_NODES];
__device__ int   g_srcs[N_EDGES];
__device__ float g_scale[N_EDGES];
__device__ int   g_is32;
__device__ int   g_bsum[NB];
__device__ int   g_boff[NB];

// ---------------- init: zero degree histogram + detect edge_index dtype ----------------
__global__ __launch_bounds__(256) void init_kernel(const int* __restrict__ ei32) {
    int i = blockIdx.x * 256 + threadIdx.x;
    if (i < N_NODES) g_deg[i] = 0;
    if (blockIdx.x == 0) {
        int nz = 0;
        for (int s = threadIdx.x; s < 4096; s += 256)
            nz |= (ei32[2 * s + 1] != 0);
        nz = __syncthreads_or(nz);
        if (threadIdx.x == 0) g_is32 = nz;
    }
}

__device__ __forceinline__ int load_idx(const void* ei, int pos) {
    if (g_is32) return ((const int*)ei)[pos];
    return (int)((const long long*)ei)[pos];
}

__global__ void count_kernel(const void* __restrict__ ei) {
    int e = blockIdx.x * blockDim.x + threadIdx.x;
    if (e >= N_EDGES) return;
    int dst = load_idx(ei, N_EDGES + e);
    if ((unsigned)dst < (unsigned)N_NODES) atomicAdd(&g_deg[dst], 1);
}

__global__ __launch_bounds__(256) void bsum_kernel() {
    int i = blockIdx.x * 256 + threadIdx.x;
    int v = (i < N_NODES) ? g_deg[i] : 0;
#pragma unroll
    for (int off = 16; off > 0; off >>= 1)
        v += __shfl_down_sync(0xffffffffu, v, off);
    __shared__ int ws[8];
    int wid = threadIdx.x >> 5, lane = threadIdx.x & 31;
    if (lane == 0) ws[wid] = v;
    __syncthreads();
    if (threadIdx.x == 0) {
        int s = 0;
#pragma unroll
        for (int w = 0; w < 8; w++) s += ws[w];
        g_bsum[blockIdx.x] = s;
    }
}

__global__ __launch_bounds__(256) void bscan_kernel() {
    int t = threadIdx.x;
    int lane = t & 31, wid = t >> 5;
    int v = (t < NB) ? g_bsum[t] : 0;
    int orig = v;
#pragma unroll
    for (int off = 1; off < 32; off <<= 1) {
        int u = __shfl_up_sync(0xffffffffu, v, off);
        if (lane >= off) v += u;
    }
    __shared__ int wsum[8];
    if (lane == 31) wsum[wid] = v;
    __syncthreads();
    if (wid == 0) {
        int s = (lane < 8) ? wsum[lane] : 0;
#pragma unroll
        for (int off = 1; off < 8; off <<= 1) {
            int u = __shfl_up_sync(0xffffffffu, s, off);
            if (lane >= off) s += u;
        }
        if (lane < 8) wsum[lane] = s;
    }
    __syncthreads();
    int incl = v + (wid > 0 ? wsum[wid - 1] : 0);
    if (t < NB) g_boff[t] = incl - orig;
}

__global__ __launch_bounds__(256) void rowptr_kernel() {
    int i = blockIdx.x * 256 + threadIdx.x;
    int lane = threadIdx.x & 31, wid = threadIdx.x >> 5;
    int v = (i < N_NODES) ? g_deg[i] : 0;
    int orig = v;
#pragma unroll
    for (int off = 1; off < 32; off <<= 1) {
        int u = __shfl_up_sync(0xffffffffu, v, off);
        if (lane >= off) v += u;
    }
    __shared__ int wsum[8];
    if (lane == 31) wsum[wid] = v;
    __syncthreads();
    if (wid == 0) {
        int s = (lane < 8) ? wsum[lane] : 0;
#pragma unroll
        for (int off = 1; off < 8; off <<= 1) {
            int u = __shfl_up_sync(0xffffffffu, s, off);
            if (lane >= off) s += u;
        }
        if (lane < 8) wsum[lane] = s;
    }
    __syncthreads();
    int incl = v + (wid > 0 ? wsum[wid - 1] : 0);
    int excl = incl - orig + g_boff[blockIdx.x];
    if (i < N_NODES) {
        g_rowptr[i] = excl;
        g_cursor[i] = excl;
        if (i == N_NODES - 1) g_rowptr[N_NODES] = excl + orig;
    }
}

__global__ void fill_kernel(const void* __restrict__ ei,
                            const float* __restrict__ ea) {
    int e = blockIdx.x * blockDim.x + threadIdx.x;
    if (e >= N_EDGES) return;
    int src = load_idx(ei, e);
    int dst = load_idx(ei, N_EDGES + e);
    if ((unsigned)dst >= (unsigned)N_NODES) return;
    if ((unsigned)src >= (unsigned)N_NODES) return;
    int pos = atomicAdd(&g_cursor[dst], 1);
    g_srcs[pos]  = src;
    g_scale[pos] = 1.0f / ea[e];
}

// ---------------- f32 -> bf16 hi/lo split converters ----------------
__device__ __forceinline__ void split_bf16(float f, unsigned short& hi, unsigned short& lo) {
    __nv_bfloat16 h = __float2bfloat16(f);
    float r = f - __bfloat162float(h);
    hi = __bfloat16_as_ushort(h);
    lo = __bfloat16_as_ushort(__float2bfloat16(r));
}

__global__ __launch_bounds__(256) void conv_x_kernel(const float* __restrict__ x) {
    int i = blockIdx.x * 256 + threadIdx.x;      // float4 index
    if (i * 4 >= N_NODES * D) return;
    float4 v = reinterpret_cast<const float4*>(x)[i];
    ushort4 hi, lo;
    split_bf16(v.x, hi.x, lo.x); split_bf16(v.y, hi.y, lo.y);
    split_bf16(v.z, hi.z, lo.z); split_bf16(v.w, hi.w, lo.w);
    reinterpret_cast<ushort4*>(g_xhi)[i] = hi;
    reinterpret_cast<ushort4*>(g_xlo)[i] = lo;
}

__global__ __launch_bounds__(256) void conv_w_kernel(const float* __restrict__ W1,
                                                     const float* __restrict__ W2) {
    int i = blockIdx.x * 256 + threadIdx.x;      // 0..8191 (two 4096 float4 sets)
    if (i >= 8192) return;
    const float* src = (i < 4096) ? W1 : W2;
    unsigned short* dh = (i < 4096) ? g_w1hi : g_w2hi;
    unsigned short* dl = (i < 4096) ? g_w1lo : g_w2lo;
    int j = i & 4095;
    float4 v = reinterpret_cast<const float4*>(src)[j];
    ushort4 hi, lo;
    split_bf16(v.x, hi.x, lo.x); split_bf16(v.y, hi.y, lo.y);
    split_bf16(v.z, hi.z, lo.z); split_bf16(v.w, hi.w, lo.w);
    reinterpret_cast<ushort4*>(dh)[j] = hi;
    reinterpret_cast<ushort4*>(dl)[j] = lo;
}

// ---------------- tensor-core GEMM via mma.sync (HMMA bf16, 3-term split) ----------------
// CTA: 64x128 tile (grid 625, no guards), 8 warps (2m x 4n), warp tile 32x32.
// Single K=128 chunk, cp.async bulk prefetch, one sync. SP=136 pad (conflict-free ldmatrix).
// Epilogue converts fp32 acc -> fp16 g_h (halves downstream gather traffic).
#define SP 136                         // padded row stride (bf16 elems)
#define A_TILE_B (64 * SP * 2)         // 17408 bytes
#define B_TILE_B (128 * SP * 2)        // 34816 bytes
#define OFF_AHI 0
#define OFF_ALO (A_TILE_B)
#define OFF_BHI (2 * A_TILE_B)
#define OFF_BLO (2 * A_TILE_B + B_TILE_B)
#define GEMM_SMEM (2 * A_TILE_B + 2 * B_TILE_B)   // 104448

__device__ __forceinline__ void ldsm4(uint32_t* r, uint32_t addr) {
    asm volatile("ldmatrix.sync.aligned.m8n8.x4.shared.b16 {%0,%1,%2,%3}, [%4];"
                 : "=r"(r[0]), "=r"(r[1]), "=r"(r[2]), "=r"(r[3]) : "r"(addr));
}
__device__ __forceinline__ void mma16816(float* d, const uint32_t* a, uint32_t b0, uint32_t b1) {
    asm volatile(
        "mma.sync.aligned.m16n8k16.row.col.f32.bf16.bf16.f32 "
        "{%0,%1,%2,%3}, {%4,%5,%6,%7}, {%8,%9}, {%0,%1,%2,%3};"
        : "+f"(d[0]), "+f"(d[1]), "+f"(d[2]), "+f"(d[3])
        : "r"(a[0]), "r"(a[1]), "r"(a[2]), "r"(a[3]), "r"(b0), "r"(b1));
}
__device__ __forceinline__ void cp16(uint32_t saddr, const void* gptr) {
    asm volatile("cp.async.cg.shared.global [%0], [%1], 16;" :: "r"(saddr), "l"(gptr));
}

__global__ __launch_bounds__(256, 2) void gemm_mma_kernel(int layer) {
    extern __shared__ char smem[];
    uint32_t sb;
    asm("{ .reg .u64 t; cvta.to.shared.u64 t, %1; cvt.u32.u64 %0, t; }" : "=r"(sb) : "l"(smem));
    const int tid  = threadIdx.x;
    const int wid  = tid >> 5;
    const int lane = tid & 31;
    const int lane8 = lane & 7;
    const int g     = lane >> 3;
    const int m0 = (wid & 1) * 32;       // 2 m-groups of 32 rows
    const int n0 = (wid >> 1) * 32;      // 4 n-groups of 32 cols
    const int block_row = blockIdx.x * 64;

    const unsigned short* Ah = (layer == 0) ? g_xhi : g_yhi;
    const unsigned short* Al = (layer == 0) ? g_xlo : g_ylo;
    const unsigned short* Bh = (layer == 0) ? g_w1hi : g_w2hi;
    const unsigned short* Bl = (layer == 0) ? g_w1lo : g_w2lo;

    // ---- issue all tile loads via cp.async (max MLP, zero register staging) ----
#pragma unroll
    for (int it = 0; it < 4; it++) {
        int idx = tid + it * 256;
        int r = idx >> 4;                // 0..63
        int c = (idx & 15) * 8;          // 0..120
        int gr = block_row + r;
        uint32_t so = (uint32_t)(r * SP + c) * 2;
        cp16(sb + OFF_AHI + so, Ah + (size_t)gr * D + c);
        cp16(sb + OFF_ALO + so, Al + (size_t)gr * D + c);
    }
#pragma unroll
    for (int it = 0; it < 8; it++) {
        int idx = tid + it * 256;
        int r = idx >> 4;                // 0..127
        int c = (idx & 15) * 8;
        uint32_t so = (uint32_t)(r * SP + c) * 2;
        cp16(sb + OFF_BHI + so, Bh + (size_t)r * D + c);
        cp16(sb + OFF_BLO + so, Bl + (size_t)r * D + c);
    }
    asm volatile("cp.async.commit_group;" ::: "memory");

    float acc[2][4][4];
#pragma unroll
    for (int i = 0; i < 2; i++)
#pragma unroll
        for (int j = 0; j < 4; j++)
#pragma unroll
            for (int c = 0; c < 4; c++) acc[i][j][c] = 0.0f;

    asm volatile("cp.async.wait_group 0;" ::: "memory");
    __syncthreads();

#pragma unroll
    for (int k16 = 0; k16 < 8; k16++) {
        const int k0 = k16 * 16;
        uint32_t ahi[2][4], alo[2][4];
#pragma unroll
        for (int mi = 0; mi < 2; mi++) {
            int arow = m0 + mi * 16 + ((g & 1) << 3) + lane8;
            int acol = k0 + ((g >> 1) << 3);
            uint32_t ao = (uint32_t)(arow * SP + acol) * 2;
            ldsm4(ahi[mi], sb + OFF_AHI + ao);
            ldsm4(alo[mi], sb + OFF_ALO + ao);
        }
#pragma unroll
        for (int jj = 0; jj < 2; jj++) {
            int brow = n0 + jj * 16 + ((g >> 1) << 3) + lane8;
            int bcol = k0 + ((g & 1) << 3);
            uint32_t bo = (uint32_t)(brow * SP + bcol) * 2;
            uint32_t bh[4], bl[4];
            ldsm4(bh, sb + OFF_BHI + bo);
            ldsm4(bl, sb + OFF_BLO + bo);
#pragma unroll
            for (int f = 0; f < 2; f++) {
                uint32_t bh0 = bh[2 * f], bh1 = bh[2 * f + 1];
                uint32_t bl0 = bl[2 * f], bl1 = bl[2 * f + 1];
#pragma unroll
                for (int mi = 0; mi < 2; mi++) {
                    float* d = acc[mi][jj * 2 + f];
                    mma16816(d, ahi[mi], bh0, bh1);   // hi*hi
                    mma16816(d, ahi[mi], bl0, bl1);   // hi*lo
                    mma16816(d, alo[mi], bh0, bh1);   // lo*hi
                }
            }
        }
    }

    // epilogue: write fp16 to g_h (no guards: 40000 % 64 == 0)
#pragma unroll
    for (int mi = 0; mi < 2; mi++) {
#pragma unroll
        for (int j = 0; j < 4; j++) {
            int row = block_row + m0 + mi * 16 + (lane >> 2);
            int col = n0 + j * 8 + (lane & 3) * 2;
            float* d = acc[mi][j];
            *reinterpret_cast<__half2*>((__half*)g_h + (size_t)row * D + col) =
                __floats2half2_rn(d[0], d[1]);
            *reinterpret_cast<__half2*>((__half*)g_h + (size_t)(row + 8) * D + col) =
                __floats2half2_rn(d[2], d[3]);
        }
    }
}

// ---------------- aggregate: relu( sum_{e in CSR[n]} g_h[src_e]*scale_e + bias ) ----------------
// g_h is fp16 (8B per lane per edge); accumulate fp32.
// layer 0 -> writes bf16 hi/lo split (g_yhi/g_ylo); layer 1 -> writes fp32 out_ext.
__global__ __launch_bounds__(256) void agg_kernel(const float* __restrict__ bias,
                                                  float* __restrict__ out_ext,
                                                  int layer) {
    int warp = (blockIdx.x * blockDim.x + threadIdx.x) >> 5;
    int lane = threadIdx.x & 31;
    if (warp >= N_NODES) return;
    const __half* H = (const __half*)g_h;
    int begin = g_rowptr[warp];
    int end   = g_rowptr[warp + 1];

    float4 acc = make_float4(0.f, 0.f, 0.f, 0.f);
    int i = begin;
    // unroll 4 for MLP=4
    for (; i + 3 < end; i += 4) {
        int   s0 = g_srcs[i],   s1 = g_srcs[i+1], s2 = g_srcs[i+2], s3 = g_srcs[i+3];
        float w0 = g_scale[i],  w1 = g_scale[i+1], w2 = g_scale[i+2], w3 = g_scale[i+3];
        uint2 r0 = *reinterpret_cast<const uint2*>(H + (size_t)s0 * D + lane * 4);
        uint2 r1 = *reinterpret_cast<const uint2*>(H + (size_t)s1 * D + lane * 4);
        uint2 r2 = *reinterpret_cast<const uint2*>(H + (size_t)s2 * D + lane * 4);
        uint2 r3 = *reinterpret_cast<const uint2*>(H + (size_t)s3 * D + lane * 4);
        float2 a0 = __half22float2(*reinterpret_cast<__half2*>(&r0.x));
        float2 b0 = __half22float2(*reinterpret_cast<__half2*>(&r0.y));
        float2 a1 = __half22float2(*reinterpret_cast<__half2*>(&r1.x));
        float2 b1 = __half22float2(*reinterpret_cast<__half2*>(&r1.y));
        float2 a2 = __half22float2(*reinterpret_cast<__half2*>(&r2.x));
        float2 b2 = __half22float2(*reinterpret_cast<__half2*>(&r2.y));
        float2 a3 = __half22float2(*reinterpret_cast<__half2*>(&r3.x));
        float2 b3 = __half22float2(*reinterpret_cast<__half2*>(&r3.y));
        acc.x += w0 * a0.x; acc.y += w0 * a0.y; acc.z += w0 * b0.x; acc.w += w0 * b0.y;
        acc.x += w1 * a1.x; acc.y += w1 * a1.y; acc.z += w1 * b1.x; acc.w += w1 * b1.y;
        acc.x += w2 * a2.x; acc.y += w2 * a2.y; acc.z += w2 * b2.x; acc.w += w2 * b2.y;
        acc.x += w3 * a3.x; acc.y += w3 * a3.y; acc.z += w3 * b3.x; acc.w += w3 * b3.y;
    }
    for (; i < end; i++) {
        int   s0 = g_srcs[i];
        float w0 = g_scale[i];
        uint2 r0 = *reinterpret_cast<const uint2*>(H + (size_t)s0 * D + lane * 4);
        float2 a0 = __half22float2(*reinterpret_cast<__half2*>(&r0.x));
        float2 b0 = __half22float2(*reinterpret_cast<__half2*>(&r0.y));
        acc.x += w0 * a0.x; acc.y += w0 * a0.y; acc.z += w0 * b0.x; acc.w += w0 * b0.y;
    }

    float4 b = *reinterpret_cast<const float4*>(bias + lane * 4);
    float4 r;
    r.x = acc.x + b.x; r.x = r.x > 0.f ? r.x : 0.f;
    r.y = acc.y + b.y; r.y = r.y > 0.f ? r.y : 0.f;
    r.z = acc.z + b.z; r.z = r.z > 0.f ? r.z : 0.f;
    r.w = acc.w + b.w; r.w = r.w > 0.f ? r.w : 0.f;

    if (layer == 1) {
        *reinterpret_cast<float4*>(out_ext + (size_t)warp * D + lane * 4) = r;
    } else {
        ushort4 hi, lo;
        split_bf16(r.x, hi.x, lo.x); split_bf16(r.y, hi.y, lo.y);
        split_bf16(r.z, hi.z, lo.z); split_bf16(r.w, hi.w, lo.w);
        size_t idx = ((size_t)warp * D + lane * 4) >> 2;
        reinterpret_cast<ushort4*>(g_yhi)[idx] = hi;
        reinterpret_cast<ushort4*>(g_ylo)[idx] = lo;
    }
}

// ---------------- launch ----------------
extern "C" void kernel_launch(void* const* d_in, const int* in_sizes, int n_in,
                              void* d_out, int out_size) {
    const float* x  = (const float*)d_in[0];
    const void*  ei = d_in[1];                 // int32 or int64, auto-detected
    const float* ea = (const float*)d_in[2];
    const float* W1 = (const float*)d_in[3];
    const float* b1 = (const float*)d_in[4];
    const float* W2 = (const float*)d_in[5];
    const float* b2 = (const float*)d_in[6];
    float* out = (float*)d_out;

    cudaFuncSetAttribute(gemm_mma_kernel, cudaFuncAttributeMaxDynamicSharedMemorySize, GEMM_SMEM);

    const int gemm_grid = N_NODES / 64;                 // 625, exact
    const int agg_grid  = (N_NODES * 32 + 255) / 256;   // 5000 blocks
    const int convx_grid = (N_NODES * D / 4 + 255) / 256;

    init_kernel<<<NB, 256>>>((const int*)ei);                         // 0
    conv_x_kernel<<<convx_grid, 256>>>(x);                            // 1
    conv_w_kernel<<<32, 256>>>(W1, W2);                               // 2
    gemm_mma_kernel<<<gemm_grid, 256, GEMM_SMEM>>>(0);                // 3  <- profiled slot
    count_kernel<<<(N_EDGES + 255) / 256, 256>>>(ei);                 // 4
    bsum_kernel<<<NB, 256>>>();                                       // 5
    bscan_kernel<<<1, 256>>>();                                       // 6
    rowptr_kernel<<<NB, 256>>>();                                     // 7
    fill_kernel<<<(N_EDGES + 255) / 256, 256>>>(ei, ea);              // 8
    agg_kernel<<<agg_grid, 256>>>(b1, out, 0);                        // 9
    gemm_mma_kernel<<<gemm_grid, 256, GEMM_SMEM>>>(1);                // 10
    agg_kernel<<<agg_grid, 256>>>(b2, out, 1);                        // 11
}

// round 14
// speedup vs baseline: 1.1685x; 1.0187x over previous
#include <cuda_runtime.h>
#include <cuda_bf16.h>
#include <cuda_fp16.h>
#include <cstdint>

#define N_NODES 40000
#define N_EDGES 640000
#define D 128
#define NB 157  // ceil(40000/256) scan blocks

// ---------------- scratch (device globals, referenced by symbol only) ----------------
__device__ __half g_h[N_NODES * D];           // GEMM output (per layer), fp16
__device__ unsigned short g_xhi[N_NODES * D]; // bf16 split of x
__device__ unsigned short g_xlo[N_NODES * D];
__device__ unsigned short g_yhi[N_NODES * D]; // bf16 split of layer-1 output
__device__ unsigned short g_ylo[N_NODES * D];
__device__ unsigned short g_w1hi[D * D], g_w1lo[D * D];
__device__ unsigned short g_w2hi[D * D], g_w2lo[D * D];
__device__ int   g_deg[N_NODES];
__device__ int   g_rowptr[N_NODES + 1];
__device__ int   g_cursor[N_NODES];
__device__ int   g_srcs[N_EDGES];
__device__ float g_scale[N_EDGES];
__device__ int   g_is32;
__device__ int   g_bsum[NB];
__device__ int   g_boff[NB];

__device__ __forceinline__ int load_idx(const void* ei, int pos) {
    if (g_is32) return ((const int*)ei)[pos];
    return (int)((const long long*)ei)[pos];
}

// ---------------- f32 -> bf16 hi/lo split ----------------
__device__ __forceinline__ void split_bf16(float f, unsigned short& hi, unsigned short& lo) {
    __nv_bfloat16 h = __float2bfloat16(f);
    float r = f - __bfloat162float(h);
    hi = __bfloat16_as_ushort(h);
    lo = __bfloat16_as_ushort(__float2bfloat16(r));
}

// ---------------- fused preamble: x-split, W-split, zero deg, dtype detect ----------------
// grid = 5000 (x) + 32 (W) + NB (deg) blocks
#define PREP_X_BLOCKS 5000
#define PREP_W_BLOCKS 32
#define PREP_GRID (PREP_X_BLOCKS + PREP_W_BLOCKS + NB)
__global__ __launch_bounds__(256) void prep_kernel(const float* __restrict__ x,
                                                   const float* __restrict__ W1,
                                                   const float* __restrict__ W2,
                                                   const int* __restrict__ ei32) {
    int b = blockIdx.x;
    if (b < PREP_X_BLOCKS) {
        int i = b * 256 + threadIdx.x;            // float4 index; 1.28M total
        if (i * 4 < N_NODES * D) {
            float4 v = reinterpret_cast<const float4*>(x)[i];
            ushort4 hi, lo;
            split_bf16(v.x, hi.x, lo.x); split_bf16(v.y, hi.y, lo.y);
            split_bf16(v.z, hi.z, lo.z); split_bf16(v.w, hi.w, lo.w);
            reinterpret_cast<ushort4*>(g_xhi)[i] = hi;
            reinterpret_cast<ushort4*>(g_xlo)[i] = lo;
        }
        return;
    }
    b -= PREP_X_BLOCKS;
    if (b < PREP_W_BLOCKS) {
        int i = b * 256 + threadIdx.x;            // 0..8191
        const float* src = (i < 4096) ? W1 : W2;
        unsigned short* dh = (i < 4096) ? g_w1hi : g_w2hi;
        unsigned short* dl = (i < 4096) ? g_w1lo : g_w2lo;
        int j = i & 4095;
        float4 v = reinterpret_cast<const float4*>(src)[j];
        ushort4 hi, lo;
        split_bf16(v.x, hi.x, lo.x); split_bf16(v.y, hi.y, lo.y);
        split_bf16(v.z, hi.z, lo.z); split_bf16(v.w, hi.w, lo.w);
        reinterpret_cast<ushort4*>(dh)[j] = hi;
        reinterpret_cast<ushort4*>(dl)[j] = lo;
        return;
    }
    b -= PREP_W_BLOCKS;
    {
        int i = b * 256 + threadIdx.x;
        if (i < N_NODES) g_deg[i] = 0;
        if (b == 0) {
            int nz = 0;
            for (int s = threadIdx.x; s < 4096; s += 256)
                nz |= (ei32[2 * s + 1] != 0);
            nz = __syncthreads_or(nz);
            if (threadIdx.x == 0) g_is32 = nz;
        }
    }
}

// ---------------- CSR build ----------------
__global__ void count_kernel(const void* __restrict__ ei) {
    int e = blockIdx.x * blockDim.x + threadIdx.x;
    if (e >= N_EDGES) return;
    int dst = load_idx(ei, N_EDGES + e);
    if ((unsigned)dst < (unsigned)N_NODES) atomicAdd(&g_deg[dst], 1);
}

__global__ __launch_bounds__(256) void bsum_kernel() {
    int i = blockIdx.x * 256 + threadIdx.x;
    int v = (i < N_NODES) ? g_deg[i] : 0;
#pragma unroll
    for (int off = 16; off > 0; off >>= 1)
        v += __shfl_down_sync(0xffffffffu, v, off);
    __shared__ int ws[8];
    int wid = threadIdx.x >> 5, lane = threadIdx.x & 31;
    if (lane == 0) ws[wid] = v;
    __syncthreads();
    if (threadIdx.x == 0) {
        int s = 0;
#pragma unroll
        for (int w = 0; w < 8; w++) s += ws[w];
        g_bsum[blockIdx.x] = s;
    }
}

__global__ __launch_bounds__(256) void bscan_kernel() {
    int t = threadIdx.x;
    int lane = t & 31, wid = t >> 5;
    int v = (t < NB) ? g_bsum[t] : 0;
    int orig = v;
#pragma unroll
    for (int off = 1; off < 32; off <<= 1) {
        int u = __shfl_up_sync(0xffffffffu, v, off);
        if (lane >= off) v += u;
    }
    __shared__ int wsum[8];
    if (lane == 31) wsum[wid] = v;
    __syncthreads();
    if (wid == 0) {
        int s = (lane < 8) ? wsum[lane] : 0;
#pragma unroll
        for (int off = 1; off < 8; off <<= 1) {
            int u = __shfl_up_sync(0xffffffffu, s, off);
            if (lane >= off) s += u;
        }
        if (lane < 8) wsum[lane] = s;
    }
    __syncthreads();
    int incl = v + (wid > 0 ? wsum[wid - 1] : 0);
    if (t < NB) g_boff[t] = incl - orig;
}

__global__ __launch_bounds__(256) void rowptr_kernel() {
    int i = blockIdx.x * 256 + threadIdx.x;
    int lane = threadIdx.x & 31, wid = threadIdx.x >> 5;
    int v = (i < N_NODES) ? g_deg[i] : 0;
    int orig = v;
#pragma unroll
    for (int off = 1; off < 32; off <<= 1) {
        int u = __shfl_up_sync(0xffffffffu, v, off);
        if (lane >= off) v += u;
    }
    __shared__ int wsum[8];
    if (lane == 31) wsum[wid] = v;
    __syncthreads();
    if (wid == 0) {
        int s = (lane < 8) ? wsum[lane] : 0;
#pragma unroll
        for (int off = 1; off < 8; off <<= 1) {
            int u = __shfl_up_sync(0xffffffffu, s, off);
            if (lane >= off) s += u;
        }
        if (lane < 8) wsum[lane] = s;
    }
    __syncthreads();
    int incl = v + (wid > 0 ? wsum[wid - 1] : 0);
    int excl = incl - orig + g_boff[blockIdx.x];
    if (i < N_NODES) {
        g_rowptr[i] = excl;
        g_cursor[i] = excl;
        if (i == N_NODES - 1) g_rowptr[N_NODES] = excl + orig;
    }
}

__global__ void fill_kernel(const void* __restrict__ ei,
                            const float* __restrict__ ea) {
    int e = blockIdx.x * blockDim.x + threadIdx.x;
    if (e >= N_EDGES) return;
    int src = load_idx(ei, e);
    int dst = load_idx(ei, N_EDGES + e);
    if ((unsigned)dst >= (unsigned)N_NODES) return;
    if ((unsigned)src >= (unsigned)N_NODES) return;
    int pos = atomicAdd(&g_cursor[dst], 1);
    g_srcs[pos]  = src;
    g_scale[pos] = 1.0f / ea[e];
}

// ---------------- tensor-core GEMM via mma.sync (HMMA bf16, 3-term split) ----------------
// CTA: 64x128 tile (grid 625, no guards), 8 warps (2m x 4n), warp tile 32x32.
// 2-stage cp.async pipeline over K halves; SP=136 pad (conflict-free ldmatrix).
// Epilogue converts fp32 acc -> fp16 g_h.
#define SP 136                         // padded row stride (bf16 elems)
#define A_TILE_B (64 * SP * 2)         // 17408 bytes
#define B_TILE_B (128 * SP * 2)        // 34816 bytes
#define OFF_AHI 0
#define OFF_ALO (A_TILE_B)
#define OFF_BHI (2 * A_TILE_B)
#define OFF_BLO (2 * A_TILE_B + B_TILE_B)
#define GEMM_SMEM (2 * A_TILE_B + 2 * B_TILE_B)   // 104448

__device__ __forceinline__ void ldsm4(uint32_t* r, uint32_t addr) {
    asm volatile("ldmatrix.sync.aligned.m8n8.x4.shared.b16 {%0,%1,%2,%3}, [%4];"
                 : "=r"(r[0]), "=r"(r[1]), "=r"(r[2]), "=r"(r[3]) : "r"(addr));
}
__device__ __forceinline__ void mma16816(float* d, const uint32_t* a, uint32_t b0, uint32_t b1) {
    asm volatile(
        "mma.sync.aligned.m16n8k16.row.col.f32.bf16.bf16.f32 "
        "{%0,%1,%2,%3}, {%4,%5,%6,%7}, {%8,%9}, {%0,%1,%2,%3};"
        : "+f"(d[0]), "+f"(d[1]), "+f"(d[2]), "+f"(d[3])
        : "r"(a[0]), "r"(a[1]), "r"(a[2]), "r"(a[3]), "r"(b0), "r"(b1));
}
__device__ __forceinline__ void cp16(uint32_t saddr, const void* gptr) {
    asm volatile("cp.async.cg.shared.global [%0], [%1], 16;" :: "r"(saddr), "l"(gptr));
}

__global__ __launch_bounds__(256, 2) void gemm_mma_kernel(int layer) {
    extern __shared__ char smem[];
    uint32_t sb;
    asm("{ .reg .u64 t; cvta.to.shared.u64 t, %1; cvt.u32.u64 %0, t; }" : "=r"(sb) : "l"(smem));
    const int tid  = threadIdx.x;
    const int wid  = tid >> 5;
    const int lane = tid & 31;
    const int lane8 = lane & 7;
    const int g     = lane >> 3;
    const int m0 = (wid & 1) * 32;       // 2 m-groups of 32 rows
    const int n0 = (wid >> 1) * 32;      // 4 n-groups of 32 cols
    const int block_row = blockIdx.x * 64;

    const unsigned short* Ah = (layer == 0) ? g_xhi : g_yhi;
    const unsigned short* Al = (layer == 0) ? g_xlo : g_ylo;
    const unsigned short* Bh = (layer == 0) ? g_w1hi : g_w2hi;
    const unsigned short* Bl = (layer == 0) ? g_w1lo : g_w2lo;

    // ---- 2-stage pipelined loads: group per K-half (64 bf16 cols = 8 uint4) ----
#pragma unroll
    for (int grp = 0; grp < 2; grp++) {
        const int kb = grp * 64;     // bf16 column base
        // A tiles: 64 rows x 64 cols = 512 uint4 each; 2/thread each
#pragma unroll
        for (int it = 0; it < 2; it++) {
            int idx = tid + it * 256;
            int r = idx >> 3;              // 0..63
            int c = kb + (idx & 7) * 8;    // within half
            int gr = block_row + r;
            uint32_t so = (uint32_t)(r * SP + c) * 2;
            cp16(sb + OFF_AHI + so, Ah + (size_t)gr * D + c);
            cp16(sb + OFF_ALO + so, Al + (size_t)gr * D + c);
        }
        // B tiles: 128 rows x 64 cols = 1024 uint4 each; 4/thread each
#pragma unroll
        for (int it = 0; it < 4; it++) {
            int idx = tid + it * 256;
            int r = idx >> 3;              // 0..127
            int c = kb + (idx & 7) * 8;
            uint32_t so = (uint32_t)(r * SP + c) * 2;
            cp16(sb + OFF_BHI + so, Bh + (size_t)r * D + c);
            cp16(sb + OFF_BLO + so, Bl + (size_t)r * D + c);
        }
        asm volatile("cp.async.commit_group;" ::: "memory");
    }

    float acc[2][4][4];
#pragma unroll
    for (int i = 0; i < 2; i++)
#pragma unroll
        for (int j = 0; j < 4; j++)
#pragma unroll
            for (int c = 0; c < 4; c++) acc[i][j][c] = 0.0f;

    asm volatile("cp.async.wait_group 1;" ::: "memory");  // first half landed
    __syncthreads();

#pragma unroll
    for (int half = 0; half < 2; half++) {
        if (half == 1) {
            asm volatile("cp.async.wait_group 0;" ::: "memory");
            __syncthreads();
        }
#pragma unroll
        for (int kq = 0; kq < 4; kq++) {
            const int k0 = half * 64 + kq * 16;
            uint32_t ahi[2][4], alo[2][4];
#pragma unroll
            for (int mi = 0; mi < 2; mi++) {
                int arow = m0 + mi * 16 + ((g & 1) << 3) + lane8;
                int acol = k0 + ((g >> 1) << 3);
                uint32_t ao = (uint32_t)(arow * SP + acol) * 2;
                ldsm4(ahi[mi], sb + OFF_AHI + ao);
                ldsm4(alo[mi], sb + OFF_ALO + ao);
            }
#pragma unroll
            for (int jj = 0; jj < 2; jj++) {
                int brow = n0 + jj * 16 + ((g >> 1) << 3) + lane8;
                int bcol = k0 + ((g & 1) << 3);
                uint32_t bo = (uint32_t)(brow * SP + bcol) * 2;
                uint32_t bh[4], bl[4];
                ldsm4(bh, sb + OFF_BHI + bo);
                ldsm4(bl, sb + OFF_BLO + bo);
#pragma unroll
                for (int f = 0; f < 2; f++) {
                    uint32_t bh0 = bh[2 * f], bh1 = bh[2 * f + 1];
                    uint32_t bl0 = bl[2 * f], bl1 = bl[2 * f + 1];
#pragma unroll
                    for (int mi = 0; mi < 2; mi++) {
                        float* d = acc[mi][jj * 2 + f];
                        mma16816(d, ahi[mi], bh0, bh1);   // hi*hi
                        mma16816(d, ahi[mi], bl0, bl1);   // hi*lo
                        mma16816(d, alo[mi], bh0, bh1);   // lo*hi
                    }
                }
            }
        }
    }

    // epilogue: write fp16 to g_h (no guards: 40000 % 64 == 0)
#pragma unroll
    for (int mi = 0; mi < 2; mi++) {
#pragma unroll
        for (int j = 0; j < 4; j++) {
            int row = block_row + m0 + mi * 16 + (lane >> 2);
            int col = n0 + j * 8 + (lane & 3) * 2;
            float* d = acc[mi][j];
            *reinterpret_cast<__half2*>((__half*)g_h + (size_t)row * D + col) =
                __floats2half2_rn(d[0], d[1]);
            *reinterpret_cast<__half2*>((__half*)g_h + (size_t)(row + 8) * D + col) =
                __floats2half2_rn(d[2], d[3]);
        }
    }
}

// ---------------- aggregate: relu( sum_{e in CSR[n]} g_h[src_e]*scale_e + bias ) ----------------
__global__ __launch_bounds__(256) void agg_kernel(const float* __restrict__ bias,
                                                  float* __restrict__ out_ext,
                                                  int layer) {
    int warp = (blockIdx.x * blockDim.x + threadIdx.x) >> 5;
    int lane = threadIdx.x & 31;
    if (warp >= N_NODES) return;
    const __half* H = (const __half*)g_h;
    int begin = g_rowptr[warp];
    int end   = g_rowptr[warp + 1];

    float4 acc = make_float4(0.f, 0.f, 0.f, 0.f);
    int i = begin;
    for (; i + 3 < end; i += 4) {
        int   s0 = g_srcs[i],   s1 = g_srcs[i+1], s2 = g_srcs[i+2], s3 = g_srcs[i+3];
        float w0 = g_scale[i],  w1 = g_scale[i+1], w2 = g_scale[i+2], w3 = g_scale[i+3];
        uint2 r0 = *reinterpret_cast<const uint2*>(H + (size_t)s0 * D + lane * 4);
        uint2 r1 = *reinterpret_cast<const uint2*>(H + (size_t)s1 * D + lane * 4);
        uint2 r2 = *reinterpret_cast<const uint2*>(H + (size_t)s2 * D + lane * 4);
        uint2 r3 = *reinterpret_cast<const uint2*>(H + (size_t)s3 * D + lane * 4);
        float2 a0 = __half22float2(*reinterpret_cast<__half2*>(&r0.x));
        float2 b0 = __half22float2(*reinterpret_cast<__half2*>(&r0.y));
        float2 a1 = __half22float2(*reinterpret_cast<__half2*>(&r1.x));
        float2 b1 = __half22float2(*reinterpret_cast<__half2*>(&r1.y));
        float2 a2 = __half22float2(*reinterpret_cast<__half2*>(&r2.x));
        float2 b2 = __half22float2(*reinterpret_cast<__half2*>(&r2.y));
        float2 a3 = __half22float2(*reinterpret_cast<__half2*>(&r3.x));
        float2 b3 = __half22float2(*reinterpret_cast<__half2*>(&r3.y));
        acc.x += w0 * a0.x; acc.y += w0 * a0.y; acc.z += w0 * b0.x; acc.w += w0 * b0.y;
        acc.x += w1 * a1.x; acc.y += w1 * a1.y; acc.z += w1 * b1.x; acc.w += w1 * b1.y;
        acc.x += w2 * a2.x; acc.y += w2 * a2.y; acc.z += w2 * b2.x; acc.w += w2 * b2.y;
        acc.x += w3 * a3.x; acc.y += w3 * a3.y; acc.z += w3 * b3.x; acc.w += w3 * b3.y;
    }
    for (; i < end; i++) {
        int   s0 = g_srcs[i];
        float w0 = g_scale[i];
        uint2 r0 = *reinterpret_cast<const uint2*>(H + (size_t)s0 * D + lane * 4);
        float2 a0 = __half22float2(*reinterpret_cast<__half2*>(&r0.x));
        float2 b0 = __half22float2(*reinterpret_cast<__half2*>(&r0.y));
        acc.x += w0 * a0.x; acc.y += w0 * a0.y; acc.z += w0 * b0.x; acc.w += w0 * b0.y;
    }

    float4 b = *reinterpret_cast<const float4*>(bias + lane * 4);
    float4 r;
    r.x = acc.x + b.x; r.x = r.x > 0.f ? r.x : 0.f;
    r.y = acc.y + b.y; r.y = r.y > 0.f ? r.y : 0.f;
    r.z = acc.z + b.z; r.z = r.z > 0.f ? r.z : 0.f;
    r.w = acc.w + b.w; r.w = r.w > 0.f ? r.w : 0.f;

    if (layer == 1) {
        *reinterpret_cast<float4*>(out_ext + (size_t)warp * D + lane * 4) = r;
    } else {
        ushort4 hi, lo;
        split_bf16(r.x, hi.x, lo.x); split_bf16(r.y, hi.y, lo.y);
        split_bf16(r.z, hi.z, lo.z); split_bf16(r.w, hi.w, lo.w);
        size_t idx = ((size_t)warp * D + lane * 4) >> 2;
        reinterpret_cast<ushort4*>(g_yhi)[idx] = hi;
        reinterpret_cast<ushort4*>(g_ylo)[idx] = lo;
    }
}

// ---------------- launch ----------------
extern "C" void kernel_launch(void* const* d_in, const int* in_sizes, int n_in,
                              void* d_out, int out_size) {
    const float* x  = (const float*)d_in[0];
    const void*  ei = d_in[1];                 // int32 or int64, auto-detected
    const float* ea = (const float*)d_in[2];
    const float* W1 = (const float*)d_in[3];
    const float* b1 = (const float*)d_in[4];
    const float* W2 = (const float*)d_in[5];
    const float* b2 = (const float*)d_in[6];
    float* out = (float*)d_out;

    cudaFuncSetAttribute(gemm_mma_kernel, cudaFuncAttributeMaxDynamicSharedMemorySize, GEMM_SMEM);

    const int gemm_grid = N_NODES / 64;                 // 625, exact
    const int agg_grid  = (N_NODES * 32 + 255) / 256;   // 5000 blocks

    prep_kernel<<<PREP_GRID, 256>>>(x, W1, W2, (const int*)ei);       // 0
    count_kernel<<<(N_EDGES + 255) / 256, 256>>>(ei);                 // 1
    bsum_kernel<<<NB, 256>>>();                                       // 2
    gemm_mma_kernel<<<gemm_grid, 256, GEMM_SMEM>>>(0);                // 3  <- profiled slot
    bscan_kernel<<<1, 256>>>();                                       // 4
    rowptr_kernel<<<NB, 256>>>();                                     // 5
    fill_kernel<<<(N_EDGES + 255) / 256, 256>>>(ei, ea);              // 6
    agg_kernel<<<agg_grid, 256>>>(b1, out, 0);                        // 7
    gemm_mma_kernel<<<gemm_grid, 256, GEMM_SMEM>>>(1);                // 8
    agg_kernel<<<agg_grid, 256>>>(b2, out, 1);                        // 9
}

// round 15
// speedup vs baseline: 1.3703x; 1.1726x over previous
#include <cuda_runtime.h>
#include <cuda_bf16.h>
#include <cuda_fp16.h>
#include <cstdint>

#define N_NODES 40000
#define N_EDGES 640000
#define D 128
#define NB 157  // ceil(40000/256) scan blocks

// ---------------- scratch (device globals, referenced by symbol only) ----------------
__device__ __half g_h[N_NODES * D];     // GEMM output (per layer), fp16
__device__ __half g_xh[N_NODES * D];    // fp16 x
__device__ __half g_yh[N_NODES * D];    // fp16 layer-1 output
__device__ __half g_w1h[D * D], g_w2h[D * D];
__device__ int   g_deg[N_NODES];
__device__ int   g_rowptr[N_NODES + 1];
__device__ int   g_cursor[N_NODES];
__device__ int   g_srcs[N_EDGES];
__device__ float g_scale[N_EDGES];
__device__ int   g_is32;
__device__ int   g_bsum[NB];
__device__ int   g_boff[NB];

__device__ __forceinline__ int load_idx(const void* ei, int pos) {
    if (g_is32) return ((const int*)ei)[pos];
    return (int)((const long long*)ei)[pos];
}

// ---------------- fused preamble: x->fp16, W->fp16, zero deg, dtype detect ----------------
#define PREP_X_BLOCKS 5000
#define PREP_W_BLOCKS 32
#define PREP_GRID (PREP_X_BLOCKS + PREP_W_BLOCKS + NB)
__global__ __launch_bounds__(256) void prep_kernel(const float* __restrict__ x,
                                                   const float* __restrict__ W1,
                                                   const float* __restrict__ W2,
                                                   const int* __restrict__ ei32) {
    int b = blockIdx.x;
    if (b < PREP_X_BLOCKS) {
        int i = b * 256 + threadIdx.x;            // float4 index; 1.28M total
        if (i * 4 < N_NODES * D) {
            float4 v = reinterpret_cast<const float4*>(x)[i];
            __half2 h0 = __floats2half2_rn(v.x, v.y);
            __half2 h1 = __floats2half2_rn(v.z, v.w);
            reinterpret_cast<__half2*>(g_xh)[2 * i]     = h0;
            reinterpret_cast<__half2*>(g_xh)[2 * i + 1] = h1;
        }
        return;
    }
    b -= PREP_X_BLOCKS;
    if (b < PREP_W_BLOCKS) {
        int i = b * 256 + threadIdx.x;            // 0..8191
        const float* src = (i < 4096) ? W1 : W2;
        __half* dh = (i < 4096) ? g_w1h : g_w2h;
        int j = i & 4095;
        float4 v = reinterpret_cast<const float4*>(src)[j];
        __half2 h0 = __floats2half2_rn(v.x, v.y);
        __half2 h1 = __floats2half2_rn(v.z, v.w);
        reinterpret_cast<__half2*>(dh)[2 * j]     = h0;
        reinterpret_cast<__half2*>(dh)[2 * j + 1] = h1;
        return;
    }
    b -= PREP_W_BLOCKS;
    {
        int i = b * 256 + threadIdx.x;
        if (i < N_NODES) g_deg[i] = 0;
        if (b == 0) {
            int nz = 0;
            for (int s = threadIdx.x; s < 4096; s += 256)
                nz |= (ei32[2 * s + 1] != 0);
            nz = __syncthreads_or(nz);
            if (threadIdx.x == 0) g_is32 = nz;
        }
    }
}

// ---------------- CSR build ----------------
__global__ void count_kernel(const void* __restrict__ ei) {
    int e = blockIdx.x * blockDim.x + threadIdx.x;
    if (e >= N_EDGES) return;
    int dst = load_idx(ei, N_EDGES + e);
    if ((unsigned)dst < (unsigned)N_NODES) atomicAdd(&g_deg[dst], 1);
}

__global__ __launch_bounds__(256) void bsum_kernel() {
    int i = blockIdx.x * 256 + threadIdx.x;
    int v = (i < N_NODES) ? g_deg[i] : 0;
#pragma unroll
    for (int off = 16; off > 0; off >>= 1)
        v += __shfl_down_sync(0xffffffffu, v, off);
    __shared__ int ws[8];
    int wid = threadIdx.x >> 5, lane = threadIdx.x & 31;
    if (lane == 0) ws[wid] = v;
    __syncthreads();
    if (threadIdx.x == 0) {
        int s = 0;
#pragma unroll
        for (int w = 0; w < 8; w++) s += ws[w];
        g_bsum[blockIdx.x] = s;
    }
}

__global__ __launch_bounds__(256) void bscan_kernel() {
    int t = threadIdx.x;
    int lane = t & 31, wid = t >> 5;
    int v = (t < NB) ? g_bsum[t] : 0;
    int orig = v;
#pragma unroll
    for (int off = 1; off < 32; off <<= 1) {
        int u = __shfl_up_sync(0xffffffffu, v, off);
        if (lane >= off) v += u;
    }
    __shared__ int wsum[8];
    if (lane == 31) wsum[wid] = v;
    __syncthreads();
    if (wid == 0) {
        int s = (lane < 8) ? wsum[lane] : 0;
#pragma unroll
        for (int off = 1; off < 8; off <<= 1) {
            int u = __shfl_up_sync(0xffffffffu, s, off);
            if (lane >= off) s += u;
        }
        if (lane < 8) wsum[lane] = s;
    }
    __syncthreads();
    int incl = v + (wid > 0 ? wsum[wid - 1] : 0);
    if (t < NB) g_boff[t] = incl - orig;
}

__global__ __launch_bounds__(256) void rowptr_kernel() {
    int i = blockIdx.x * 256 + threadIdx.x;
    int lane = threadIdx.x & 31, wid = threadIdx.x >> 5;
    int v = (i < N_NODES) ? g_deg[i] : 0;
    int orig = v;
#pragma unroll
    for (int off = 1; off < 32; off <<= 1) {
        int u = __shfl_up_sync(0xffffffffu, v, off);
        if (lane >= off) v += u;
    }
    __shared__ int wsum[8];
    if (lane == 31) wsum[wid] = v;
    __syncthreads();
    if (wid == 0) {
        int s = (lane < 8) ? wsum[lane] : 0;
#pragma unroll
        for (int off = 1; off < 8; off <<= 1) {
            int u = __shfl_up_sync(0xffffffffu, s, off);
            if (lane >= off) s += u;
        }
        if (lane < 8) wsum[lane] = s;
    }
    __syncthreads();
    int incl = v + (wid > 0 ? wsum[wid - 1] : 0);
    int excl = incl - orig + g_boff[blockIdx.x];
    if (i < N_NODES) {
        g_rowptr[i] = excl;
        g_cursor[i] = excl;
        if (i == N_NODES - 1) g_rowptr[N_NODES] = excl + orig;
    }
}

__global__ void fill_kernel(const void* __restrict__ ei,
                            const float* __restrict__ ea) {
    int e = blockIdx.x * blockDim.x + threadIdx.x;
    if (e >= N_EDGES) return;
    int src = load_idx(ei, e);
    int dst = load_idx(ei, N_EDGES + e);
    if ((unsigned)dst >= (unsigned)N_NODES) return;
    if ((unsigned)src >= (unsigned)N_NODES) return;
    int pos = atomicAdd(&g_cursor[dst], 1);
    g_srcs[pos]  = src;
    g_scale[pos] = 1.0f / ea[e];
}

// ---------------- fp16 tensor-core GEMM via mma.sync: g_h = X @ W^T ----------------
// CTA: 64x128 tile (grid 625, no guards), 8 warps (2m x 4n), warp tile 32x32.
// Single-term fp16 mma, fp32 accumulate. smem 52224 B -> 4 CTAs/SM.
#define SP 136                         // padded row stride (fp16 elems)
#define A_TILE_B (64 * SP * 2)         // 17408 bytes
#define B_TILE_B (128 * SP * 2)        // 34816 bytes
#define OFF_A 0
#define OFF_B (A_TILE_B)
#define GEMM_SMEM (A_TILE_B + B_TILE_B)   // 52224

__device__ __forceinline__ void ldsm4(uint32_t* r, uint32_t addr) {
    asm volatile("ldmatrix.sync.aligned.m8n8.x4.shared.b16 {%0,%1,%2,%3}, [%4];"
                 : "=r"(r[0]), "=r"(r[1]), "=r"(r[2]), "=r"(r[3]) : "r"(addr));
}
__device__ __forceinline__ void mma16816h(float* d, const uint32_t* a, uint32_t b0, uint32_t b1) {
    asm volatile(
        "mma.sync.aligned.m16n8k16.row.col.f32.f16.f16.f32 "
        "{%0,%1,%2,%3}, {%4,%5,%6,%7}, {%8,%9}, {%0,%1,%2,%3};"
        : "+f"(d[0]), "+f"(d[1]), "+f"(d[2]), "+f"(d[3])
        : "r"(a[0]), "r"(a[1]), "r"(a[2]), "r"(a[3]), "r"(b0), "r"(b1));
}
__device__ __forceinline__ void cp16(uint32_t saddr, const void* gptr) {
    asm volatile("cp.async.cg.shared.global [%0], [%1], 16;" :: "r"(saddr), "l"(gptr));
}

__global__ __launch_bounds__(256, 4) void gemm_mma_kernel(int layer) {
    extern __shared__ char smem[];
    uint32_t sb;
    asm("{ .reg .u64 t; cvta.to.shared.u64 t, %1; cvt.u32.u64 %0, t; }" : "=r"(sb) : "l"(smem));
    const int tid  = threadIdx.x;
    const int wid  = tid >> 5;
    const int lane = tid & 31;
    const int lane8 = lane & 7;
    const int g     = lane >> 3;
    const int m0 = (wid & 1) * 32;       // 2 m-groups of 32 rows
    const int n0 = (wid >> 1) * 32;      // 4 n-groups of 32 cols
    const int block_row = blockIdx.x * 64;

    const __half* A = (layer == 0) ? g_xh : g_yh;
    const __half* B = (layer == 0) ? g_w1h : g_w2h;

    // ---- issue all tile loads via cp.async ----
    // A tile: 64 rows x 128 cols fp16 = 1024 uint4; 4 per thread
#pragma unroll
    for (int it = 0; it < 4; it++) {
        int idx = tid + it * 256;
        int r = idx >> 4;                // 0..63
        int c = (idx & 15) * 8;          // 0..120
        int gr = block_row + r;
        uint32_t so = (uint32_t)(r * SP + c) * 2;
        cp16(sb + OFF_A + so, A + (size_t)gr * D + c);
    }
    // B tile: 128 rows x 128 cols fp16 = 2048 uint4; 8 per thread
#pragma unroll
    for (int it = 0; it < 8; it++) {
        int idx = tid + it * 256;
        int r = idx >> 4;                // 0..127
        int c = (idx & 15) * 8;
        uint32_t so = (uint32_t)(r * SP + c) * 2;
        cp16(sb + OFF_B + so, B + (size_t)r * D + c);
    }
    asm volatile("cp.async.commit_group;" ::: "memory");

    float acc[2][4][4];
#pragma unroll
    for (int i = 0; i < 2; i++)
#pragma unroll
        for (int j = 0; j < 4; j++)
#pragma unroll
            for (int c = 0; c < 4; c++) acc[i][j][c] = 0.0f;

    asm volatile("cp.async.wait_group 0;" ::: "memory");
    __syncthreads();

#pragma unroll
    for (int k16 = 0; k16 < 8; k16++) {
        const int k0 = k16 * 16;
        uint32_t a[2][4];
#pragma unroll
        for (int mi = 0; mi < 2; mi++) {
            int arow = m0 + mi * 16 + ((g & 1) << 3) + lane8;
            int acol = k0 + ((g >> 1) << 3);
            uint32_t ao = (uint32_t)(arow * SP + acol) * 2;
            ldsm4(a[mi], sb + OFF_A + ao);
        }
#pragma unroll
        for (int jj = 0; jj < 2; jj++) {
            int brow = n0 + jj * 16 + ((g >> 1) << 3) + lane8;
            int bcol = k0 + ((g & 1) << 3);
            uint32_t bo = (uint32_t)(brow * SP + bcol) * 2;
            uint32_t bh[4];
            ldsm4(bh, sb + OFF_B + bo);
#pragma unroll
            for (int f = 0; f < 2; f++) {
                uint32_t b0 = bh[2 * f], b1 = bh[2 * f + 1];
#pragma unroll
                for (int mi = 0; mi < 2; mi++)
                    mma16816h(acc[mi][jj * 2 + f], a[mi], b0, b1);
            }
        }
    }

    // epilogue: write fp16 to g_h (no guards: 40000 % 64 == 0)
#pragma unroll
    for (int mi = 0; mi < 2; mi++) {
#pragma unroll
        for (int j = 0; j < 4; j++) {
            int row = block_row + m0 + mi * 16 + (lane >> 2);
            int col = n0 + j * 8 + (lane & 3) * 2;
            float* d = acc[mi][j];
            *reinterpret_cast<__half2*>((__half*)g_h + (size_t)row * D + col) =
                __floats2half2_rn(d[0], d[1]);
            *reinterpret_cast<__half2*>((__half*)g_h + (size_t)(row + 8) * D + col) =
                __floats2half2_rn(d[2], d[3]);
        }
    }
}

// ---------------- aggregate: relu( sum_{e in CSR[n]} g_h[src_e]*scale_e + bias ) ----------------
// layer 0 -> writes fp16 g_yh; layer 1 -> writes fp32 out_ext.
__global__ __launch_bounds__(256) void agg_kernel(const float* __restrict__ bias,
                                                  float* __restrict__ out_ext,
                                                  int layer) {
    int warp = (blockIdx.x * blockDim.x + threadIdx.x) >> 5;
    int lane = threadIdx.x & 31;
    if (warp >= N_NODES) return;
    const __half* H = (const __half*)g_h;
    int begin = g_rowptr[warp];
    int end   = g_rowptr[warp + 1];

    float4 acc = make_float4(0.f, 0.f, 0.f, 0.f);
    int i = begin;
    for (; i + 3 < end; i += 4) {
        int   s0 = g_srcs[i],   s1 = g_srcs[i+1], s2 = g_srcs[i+2], s3 = g_srcs[i+3];
        float w0 = g_scale[i],  w1 = g_scale[i+1], w2 = g_scale[i+2], w3 = g_scale[i+3];
        uint2 r0 = *reinterpret_cast<const uint2*>(H + (size_t)s0 * D + lane * 4);
        uint2 r1 = *reinterpret_cast<const uint2*>(H + (size_t)s1 * D + lane * 4);
        uint2 r2 = *reinterpret_cast<const uint2*>(H + (size_t)s2 * D + lane * 4);
        uint2 r3 = *reinterpret_cast<const uint2*>(H + (size_t)s3 * D + lane * 4);
        float2 a0 = __half22float2(*reinterpret_cast<__half2*>(&r0.x));
        float2 b0 = __half22float2(*reinterpret_cast<__half2*>(&r0.y));
        float2 a1 = __half22float2(*reinterpret_cast<__half2*>(&r1.x));
        float2 b1 = __half22float2(*reinterpret_cast<__half2*>(&r1.y));
        float2 a2 = __half22float2(*reinterpret_cast<__half2*>(&r2.x));
        float2 b2 = __half22float2(*reinterpret_cast<__half2*>(&r2.y));
        float2 a3 = __half22float2(*reinterpret_cast<__half2*>(&r3.x));
        float2 b3 = __half22float2(*reinterpret_cast<__half2*>(&r3.y));
        acc.x += w0 * a0.x; acc.y += w0 * a0.y; acc.z += w0 * b0.x; acc.w += w0 * b0.y;
        acc.x += w1 * a1.x; acc.y += w1 * a1.y; acc.z += w1 * b1.x; acc.w += w1 * b1.y;
        acc.x += w2 * a2.x; acc.y += w2 * a2.y; acc.z += w2 * b2.x; acc.w += w2 * b2.y;
        acc.x += w3 * a3.x; acc.y += w3 * a3.y; acc.z += w3 * b3.x; acc.w += w3 * b3.y;
    }
    for (; i < end; i++) {
        int   s0 = g_srcs[i];
        float w0 = g_scale[i];
        uint2 r0 = *reinterpret_cast<const uint2*>(H + (size_t)s0 * D + lane * 4);
        float2 a0 = __half22float2(*reinterpret_cast<__half2*>(&r0.x));
        float2 b0 = __half22float2(*reinterpret_cast<__half2*>(&r0.y));
        acc.x += w0 * a0.x; acc.y += w0 * a0.y; acc.z += w0 * b0.x; acc.w += w0 * b0.y;
    }

    float4 b = *reinterpret_cast<const float4*>(bias + lane * 4);
    float4 r;
    r.x = acc.x + b.x; r.x = r.x > 0.f ? r.x : 0.f;
    r.y = acc.y + b.y; r.y = r.y > 0.f ? r.y : 0.f;
    r.z = acc.z + b.z; r.z = r.z > 0.f ? r.z : 0.f;
    r.w = acc.w + b.w; r.w = r.w > 0.f ? r.w : 0.f;

    if (layer == 1) {
        *reinterpret_cast<float4*>(out_ext + (size_t)warp * D + lane * 4) = r;
    } else {
        size_t base = (size_t)warp * D + lane * 4;
        *reinterpret_cast<__half2*>((__half*)g_yh + base)     = __floats2half2_rn(r.x, r.y);
        *reinterpret_cast<__half2*>((__half*)g_yh + base + 2) = __floats2half2_rn(r.z, r.w);
    }
}

// ---------------- launch ----------------
extern "C" void kernel_launch(void* const* d_in, const int* in_sizes, int n_in,
                              void* d_out, int out_size) {
    const float* x  = (const float*)d_in[0];
    const void*  ei = d_in[1];                 // int32 or int64, auto-detected
    const float* ea = (const float*)d_in[2];
    const float* W1 = (const float*)d_in[3];
    const float* b1 = (const float*)d_in[4];
    const float* W2 = (const float*)d_in[5];
    const float* b2 = (const float*)d_in[6];
    float* out = (float*)d_out;

    cudaFuncSetAttribute(gemm_mma_kernel, cudaFuncAttributeMaxDynamicSharedMemorySize, GEMM_SMEM);

    const int gemm_grid = N_NODES / 64;                 // 625, exact
    const int agg_grid  = (N_NODES * 32 + 255) / 256;   // 5000 blocks

    prep_kernel<<<PREP_GRID, 256>>>(x, W1, W2, (const int*)ei);       // 0
    count_kernel<<<(N_EDGES + 255) / 256, 256>>>(ei);                 // 1
    bsum_kernel<<<NB, 256>>>();                                       // 2
    gemm_mma_kernel<<<gemm_grid, 256, GEMM_SMEM>>>(0);                // 3  <- profiled slot
    bscan_kernel<<<1, 256>>>();                                       // 4
    rowptr_kernel<<<NB, 256>>>();                                     // 5
    fill_kernel<<<(N_EDGES + 255) / 256, 256>>>(ei, ea);              // 6
    agg_kernel<<<agg_grid, 256>>>(b1, out, 0);                        // 7
    gemm_mma_kernel<<<gemm_grid, 256, GEMM_SMEM>>>(1);                // 8
    agg_kernel<<<agg_grid, 256>>>(b2, out, 1);                        // 9
}

// round 16
// speedup vs baseline: 1.4616x; 1.0667x over previous
#include <cuda_runtime.h>
#include <cuda_bf16.h>
#include <cuda_fp16.h>
#include <cstdint>

#define N_NODES 40000
#define N_EDGES 640000
#define D 128
#define NB 157  // ceil(40000/256) scan blocks

// ---------------- scratch (device globals, referenced by symbol only) ----------------
__device__ __half g_h[N_NODES * D];     // GEMM output (per layer), fp16
__device__ __half g_xh[N_NODES * D];    // fp16 x
__device__ __half g_yh[N_NODES * D];    // fp16 layer-1 output
__device__ __half g_w1h[D * D], g_w2h[D * D];
__device__ int   g_deg[N_NODES];
__device__ int   g_rowptr[N_NODES + 1];
__device__ int   g_cursor[N_NODES];
__device__ int   g_srcs[N_EDGES];
__device__ float g_scale[N_EDGES];
__device__ int   g_is32;
__device__ int   g_bsum[NB];
__device__ int   g_boff[NB];

__device__ __forceinline__ int load_idx(const void* ei, int pos) {
    if (g_is32) return ((const int*)ei)[pos];
    return (int)((const long long*)ei)[pos];
}

// ---------------- prep_init: zero deg + dtype detect (tiny; runs before fork) ----------------
__global__ __launch_bounds__(256) void prep_init_kernel(const int* __restrict__ ei32) {
    int i = blockIdx.x * 256 + threadIdx.x;
    if (i < N_NODES) g_deg[i] = 0;
    if (blockIdx.x == 0) {
        int nz = 0;
        for (int s = threadIdx.x; s < 4096; s += 256)
            nz |= (ei32[2 * s + 1] != 0);
        nz = __syncthreads_or(nz);
        if (threadIdx.x == 0) g_is32 = nz;
    }
}

// ---------------- prep_conv: x->fp16, W->fp16 (main-stream branch) ----------------
#define PREP_X_BLOCKS 5000
#define PREP_W_BLOCKS 32
#define PREP_CONV_GRID (PREP_X_BLOCKS + PREP_W_BLOCKS)
__global__ __launch_bounds__(256) void prep_conv_kernel(const float* __restrict__ x,
                                                        const float* __restrict__ W1,
                                                        const float* __restrict__ W2) {
    int b = blockIdx.x;
    if (b < PREP_X_BLOCKS) {
        int i = b * 256 + threadIdx.x;            // float4 index; 1.28M total
        if (i * 4 < N_NODES * D) {
            float4 v = reinterpret_cast<const float4*>(x)[i];
            __half2 h0 = __floats2half2_rn(v.x, v.y);
            __half2 h1 = __floats2half2_rn(v.z, v.w);
            reinterpret_cast<__half2*>(g_xh)[2 * i]     = h0;
            reinterpret_cast<__half2*>(g_xh)[2 * i + 1] = h1;
        }
        return;
    }
    b -= PREP_X_BLOCKS;
    {
        int i = b * 256 + threadIdx.x;            // 0..8191
        const float* src = (i < 4096) ? W1 : W2;
        __half* dh = (i < 4096) ? g_w1h : g_w2h;
        int j = i & 4095;
        float4 v = reinterpret_cast<const float4*>(src)[j];
        __half2 h0 = __floats2half2_rn(v.x, v.y);
        __half2 h1 = __floats2half2_rn(v.z, v.w);
        reinterpret_cast<__half2*>(dh)[2 * j]     = h0;
        reinterpret_cast<__half2*>(dh)[2 * j + 1] = h1;
    }
}

// ---------------- CSR build (side-stream branch) ----------------
__global__ void count_kernel(const void* __restrict__ ei) {
    int e = blockIdx.x * blockDim.x + threadIdx.x;
    if (e >= N_EDGES) return;
    int dst = load_idx(ei, N_EDGES + e);
    if ((unsigned)dst < (unsigned)N_NODES) atomicAdd(&g_deg[dst], 1);
}

__global__ __launch_bounds__(256) void bsum_kernel() {
    int i = blockIdx.x * 256 + threadIdx.x;
    int v = (i < N_NODES) ? g_deg[i] : 0;
#pragma unroll
    for (int off = 16; off > 0; off >>= 1)
        v += __shfl_down_sync(0xffffffffu, v, off);
    __shared__ int ws[8];
    int wid = threadIdx.x >> 5, lane = threadIdx.x & 31;
    if (lane == 0) ws[wid] = v;
    __syncthreads();
    if (threadIdx.x == 0) {
        int s = 0;
#pragma unroll
        for (int w = 0; w < 8; w++) s += ws[w];
        g_bsum[blockIdx.x] = s;
    }
}

__global__ __launch_bounds__(256) void bscan_kernel() {
    int t = threadIdx.x;
    int lane = t & 31, wid = t >> 5;
    int v = (t < NB) ? g_bsum[t] : 0;
    int orig = v;
#pragma unroll
    for (int off = 1; off < 32; off <<= 1) {
        int u = __shfl_up_sync(0xffffffffu, v, off);
        if (lane >= off) v += u;
    }
    __shared__ int wsum[8];
    if (lane == 31) wsum[wid] = v;
    __syncthreads();
    if (wid == 0) {
        int s = (lane < 8) ? wsum[lane] : 0;
#pragma unroll
        for (int off = 1; off < 8; off <<= 1) {
            int u = __shfl_up_sync(0xffffffffu, s, off);
            if (lane >= off) s += u;
        }
        if (lane < 8) wsum[lane] = s;
    }
    __syncthreads();
    int incl = v + (wid > 0 ? wsum[wid - 1] : 0);
    if (t < NB) g_boff[t] = incl - orig;
}

__global__ __launch_bounds__(256) void rowptr_kernel() {
    int i = blockIdx.x * 256 + threadIdx.x;
    int lane = threadIdx.x & 31, wid = threadIdx.x >> 5;
    int v = (i < N_NODES) ? g_deg[i] : 0;
    int orig = v;
#pragma unroll
    for (int off = 1; off < 32; off <<= 1) {
        int u = __shfl_up_sync(0xffffffffu, v, off);
        if (lane >= off) v += u;
    }
    __shared__ int wsum[8];
    if (lane == 31) wsum[wid] = v;
    __syncthreads();
    if (wid == 0) {
        int s = (lane < 8) ? wsum[lane] : 0;
#pragma unroll
        for (int off = 1; off < 8; off <<= 1) {
            int u = __shfl_up_sync(0xffffffffu, s, off);
            if (lane >= off) s += u;
        }
        if (lane < 8) wsum[lane] = s;
    }
    __syncthreads();
    int incl = v + (wid > 0 ? wsum[wid - 1] : 0);
    int excl = incl - orig + g_boff[blockIdx.x];
    if (i < N_NODES) {
        g_rowptr[i] = excl;
        g_cursor[i] = excl;
        if (i == N_NODES - 1) g_rowptr[N_NODES] = excl + orig;
    }
}

__global__ void fill_kernel(const void* __restrict__ ei,
                            const float* __restrict__ ea) {
    int e = blockIdx.x * blockDim.x + threadIdx.x;
    if (e >= N_EDGES) return;
    int src = load_idx(ei, e);
    int dst = load_idx(ei, N_EDGES + e);
    if ((unsigned)dst >= (unsigned)N_NODES) return;
    if ((unsigned)src >= (unsigned)N_NODES) return;
    int pos = atomicAdd(&g_cursor[dst], 1);
    g_srcs[pos]  = src;
    g_scale[pos] = 1.0f / ea[e];
}

// ---------------- fp16 tensor-core GEMM via mma.sync: g_h = X @ W^T ----------------
// CTA: 64x128 tile (grid 625, no guards), 8 warps (2m x 4n), warp tile 32x32.
// Single-term fp16 mma, fp32 accumulate. smem 52224 B -> 4 CTAs/SM.
#define SP 136                         // padded row stride (fp16 elems)
#define A_TILE_B (64 * SP * 2)         // 17408 bytes
#define B_TILE_B (128 * SP * 2)        // 34816 bytes
#define OFF_A 0
#define OFF_B (A_TILE_B)
#define GEMM_SMEM (A_TILE_B + B_TILE_B)   // 52224

__device__ __forceinline__ void ldsm4(uint32_t* r, uint32_t addr) {
    asm volatile("ldmatrix.sync.aligned.m8n8.x4.shared.b16 {%0,%1,%2,%3}, [%4];"
                 : "=r"(r[0]), "=r"(r[1]), "=r"(r[2]), "=r"(r[3]) : "r"(addr));
}
__device__ __forceinline__ void mma16816h(float* d, const uint32_t* a, uint32_t b0, uint32_t b1) {
    asm volatile(
        "mma.sync.aligned.m16n8k16.row.col.f32.f16.f16.f32 "
        "{%0,%1,%2,%3}, {%4,%5,%6,%7}, {%8,%9}, {%0,%1,%2,%3};"
        : "+f"(d[0]), "+f"(d[1]), "+f"(d[2]), "+f"(d[3])
        : "r"(a[0]), "r"(a[1]), "r"(a[2]), "r"(a[3]), "r"(b0), "r"(b1));
}
__device__ __forceinline__ void cp16(uint32_t saddr, const void* gptr) {
    asm volatile("cp.async.cg.shared.global [%0], [%1], 16;" :: "r"(saddr), "l"(gptr));
}

__global__ __launch_bounds__(256, 4) void gemm_mma_kernel(int layer) {
    extern __shared__ char smem[];
    uint32_t sb;
    asm("{ .reg .u64 t; cvta.to.shared.u64 t, %1; cvt.u32.u64 %0, t; }" : "=r"(sb) : "l"(smem));
    const int tid  = threadIdx.x;
    const int wid  = tid >> 5;
    const int lane = tid & 31;
    const int lane8 = lane & 7;
    const int g     = lane >> 3;
    const int m0 = (wid & 1) * 32;       // 2 m-groups of 32 rows
    const int n0 = (wid >> 1) * 32;      // 4 n-groups of 32 cols
    const int block_row = blockIdx.x * 64;

    const __half* A = (layer == 0) ? g_xh : g_yh;
    const __half* B = (layer == 0) ? g_w1h : g_w2h;

    // ---- issue all tile loads via cp.async ----
#pragma unroll
    for (int it = 0; it < 4; it++) {
        int idx = tid + it * 256;
        int r = idx >> 4;                // 0..63
        int c = (idx & 15) * 8;          // 0..120
        int gr = block_row + r;
        uint32_t so = (uint32_t)(r * SP + c) * 2;
        cp16(sb + OFF_A + so, A + (size_t)gr * D + c);
    }
#pragma unroll
    for (int it = 0; it < 8; it++) {
        int idx = tid + it * 256;
        int r = idx >> 4;                // 0..127
        int c = (idx & 15) * 8;
        uint32_t so = (uint32_t)(r * SP + c) * 2;
        cp16(sb + OFF_B + so, B + (size_t)r * D + c);
    }
    asm volatile("cp.async.commit_group;" ::: "memory");

    float acc[2][4][4];
#pragma unroll
    for (int i = 0; i < 2; i++)
#pragma unroll
        for (int j = 0; j < 4; j++)
#pragma unroll
            for (int c = 0; c < 4; c++) acc[i][j][c] = 0.0f;

    asm volatile("cp.async.wait_group 0;" ::: "memory");
    __syncthreads();

#pragma unroll
    for (int k16 = 0; k16 < 8; k16++) {
        const int k0 = k16 * 16;
        uint32_t a[2][4];
#pragma unroll
        for (int mi = 0; mi < 2; mi++) {
            int arow = m0 + mi * 16 + ((g & 1) << 3) + lane8;
            int acol = k0 + ((g >> 1) << 3);
            uint32_t ao = (uint32_t)(arow * SP + acol) * 2;
            ldsm4(a[mi], sb + OFF_A + ao);
        }
#pragma unroll
        for (int jj = 0; jj < 2; jj++) {
            int brow = n0 + jj * 16 + ((g >> 1) << 3) + lane8;
            int bcol = k0 + ((g & 1) << 3);
            uint32_t bo = (uint32_t)(brow * SP + bcol) * 2;
            uint32_t bh[4];
            ldsm4(bh, sb + OFF_B + bo);
#pragma unroll
            for (int f = 0; f < 2; f++) {
                uint32_t b0 = bh[2 * f], b1 = bh[2 * f + 1];
#pragma unroll
                for (int mi = 0; mi < 2; mi++)
                    mma16816h(acc[mi][jj * 2 + f], a[mi], b0, b1);
            }
        }
    }

    // epilogue: write fp16 to g_h (no guards: 40000 % 64 == 0)
#pragma unroll
    for (int mi = 0; mi < 2; mi++) {
#pragma unroll
        for (int j = 0; j < 4; j++) {
            int row = block_row + m0 + mi * 16 + (lane >> 2);
            int col = n0 + j * 8 + (lane & 3) * 2;
            float* d = acc[mi][j];
            *reinterpret_cast<__half2*>((__half*)g_h + (size_t)row * D + col) =
                __floats2half2_rn(d[0], d[1]);
            *reinterpret_cast<__half2*>((__half*)g_h + (size_t)(row + 8) * D + col) =
                __floats2half2_rn(d[2], d[3]);
        }
    }
}

// ---------------- aggregate: relu( sum_{e in CSR[n]} g_h[src_e]*scale_e + bias ) ----------------
// layer 0 -> writes fp16 g_yh; layer 1 -> writes fp32 out_ext.
__global__ __launch_bounds__(256) void agg_kernel(const float* __restrict__ bias,
                                                  float* __restrict__ out_ext,
                                                  int layer) {
    int warp = (blockIdx.x * blockDim.x + threadIdx.x) >> 5;
    int lane = threadIdx.x & 31;
    if (warp >= N_NODES) return;
    const __half* H = (const __half*)g_h;
    int begin = g_rowptr[warp];
    int end   = g_rowptr[warp + 1];

    float4 acc = make_float4(0.f, 0.f, 0.f, 0.f);
    int i = begin;
    for (; i + 3 < end; i += 4) {
        int   s0 = g_srcs[i],   s1 = g_srcs[i+1], s2 = g_srcs[i+2], s3 = g_srcs[i+3];
        float w0 = g_scale[i],  w1 = g_scale[i+1], w2 = g_scale[i+2], w3 = g_scale[i+3];
        uint2 r0 = *reinterpret_cast<const uint2*>(H + (size_t)s0 * D + lane * 4);
        uint2 r1 = *reinterpret_cast<const uint2*>(H + (size_t)s1 * D + lane * 4);
        uint2 r2 = *reinterpret_cast<const uint2*>(H + (size_t)s2 * D + lane * 4);
        uint2 r3 = *reinterpret_cast<const uint2*>(H + (size_t)s3 * D + lane * 4);
        float2 a0 = __half22float2(*reinterpret_cast<__half2*>(&r0.x));
        float2 b0 = __half22float2(*reinterpret_cast<__half2*>(&r0.y));
        float2 a1 = __half22float2(*reinterpret_cast<__half2*>(&r1.x));
        float2 b1 = __half22float2(*reinterpret_cast<__half2*>(&r1.y));
        float2 a2 = __half22float2(*reinterpret_cast<__half2*>(&r2.x));
        float2 b2 = __half22float2(*reinterpret_cast<__half2*>(&r2.y));
        float2 a3 = __half22float2(*reinterpret_cast<__half2*>(&r3.x));
        float2 b3 = __half22float2(*reinterpret_cast<__half2*>(&r3.y));
        acc.x += w0 * a0.x; acc.y += w0 * a0.y; acc.z += w0 * b0.x; acc.w += w0 * b0.y;
        acc.x += w1 * a1.x; acc.y += w1 * a1.y; acc.z += w1 * b1.x; acc.w += w1 * b1.y;
        acc.x += w2 * a2.x; acc.y += w2 * a2.y; acc.z += w2 * b2.x; acc.w += w2 * b2.y;
        acc.x += w3 * a3.x; acc.y += w3 * a3.y; acc.z += w3 * b3.x; acc.w += w3 * b3.y;
    }
    for (; i < end; i++) {
        int   s0 = g_srcs[i];
        float w0 = g_scale[i];
        uint2 r0 = *reinterpret_cast<const uint2*>(H + (size_t)s0 * D + lane * 4);
        float2 a0 = __half22float2(*reinterpret_cast<__half2*>(&r0.x));
        float2 b0 = __half22float2(*reinterpret_cast<__half2*>(&r0.y));
        acc.x += w0 * a0.x; acc.y += w0 * a0.y; acc.z += w0 * b0.x; acc.w += w0 * b0.y;
    }

    float4 b = *reinterpret_cast<const float4*>(bias + lane * 4);
    float4 r;
    r.x = acc.x + b.x; r.x = r.x > 0.f ? r.x : 0.f;
    r.y = acc.y + b.y; r.y = r.y > 0.f ? r.y : 0.f;
    r.z = acc.z + b.z; r.z = r.z > 0.f ? r.z : 0.f;
    r.w = acc.w + b.w; r.w = r.w > 0.f ? r.w : 0.f;

    if (layer == 1) {
        *reinterpret_cast<float4*>(out_ext + (size_t)warp * D + lane * 4) = r;
    } else {
        size_t base = (size_t)warp * D + lane * 4;
        *reinterpret_cast<__half2*>((__half*)g_yh + base)     = __floats2half2_rn(r.x, r.y);
        *reinterpret_cast<__half2*>((__half*)g_yh + base + 2) = __floats2half2_rn(r.z, r.w);
    }
}

// ---------------- launch: two-branch graph (CSR build || conv+gemm1) ----------------
extern "C" void kernel_launch(void* const* d_in, const int* in_sizes, int n_in,
                              void* d_out, int out_size) {
    const float* x  = (const float*)d_in[0];
    const void*  ei = d_in[1];                 // int32 or int64, auto-detected
    const float* ea = (const float*)d_in[2];
    const float* W1 = (const float*)d_in[3];
    const float* b1 = (const float*)d_in[4];
    const float* W2 = (const float*)d_in[5];
    const float* b2 = (const float*)d_in[6];
    float* out = (float*)d_out;

    cudaFuncSetAttribute(gemm_mma_kernel, cudaFuncAttributeMaxDynamicSharedMemorySize, GEMM_SMEM);

    const int gemm_grid = N_NODES / 64;                 // 625, exact
    const int agg_grid  = (N_NODES * 32 + 255) / 256;   // 5000 blocks
    const int edge_grid = (N_EDGES + 255) / 256;

    cudaStream_t s2;
    cudaEvent_t eFork, eJoin;
    cudaStreamCreateWithFlags(&s2, cudaStreamNonBlocking);
    cudaEventCreateWithFlags(&eFork, cudaEventDisableTiming);
    cudaEventCreateWithFlags(&eJoin, cudaEventDisableTiming);

    // prologue on main stream
    prep_init_kernel<<<NB, 256>>>((const int*)ei);

    // fork: CSR branch on s2
    cudaEventRecord(eFork, 0);
    cudaStreamWaitEvent(s2, eFork, 0);
    count_kernel<<<edge_grid, 256, 0, s2>>>(ei);
    bsum_kernel<<<NB, 256, 0, s2>>>();
    bscan_kernel<<<1, 256, 0, s2>>>();
    rowptr_kernel<<<NB, 256, 0, s2>>>();
    fill_kernel<<<edge_grid, 256, 0, s2>>>(ei, ea);

    // main branch: conversions + layer-1 GEMM (overlaps with CSR build)
    prep_conv_kernel<<<PREP_CONV_GRID, 256>>>(x, W1, W2);
    gemm_mma_kernel<<<gemm_grid, 256, GEMM_SMEM>>>(0);

    // join: agg1 needs both gemm1 (main) and fill (s2)
    cudaEventRecord(eJoin, s2);
    cudaStreamWaitEvent(0, eJoin, 0);

    agg_kernel<<<agg_grid, 256>>>(b1, out, 0);
    gemm_mma_kernel<<<gemm_grid, 256, GEMM_SMEM>>>(1);
    agg_kernel<<<agg_grid, 256>>>(b2, out, 1);

    cudaEventDestroy(eFork);
    cudaEventDestroy(eJoin);
    cudaStreamDestroy(s2);
}